// round 6
// baseline (speedup 1.0000x reference)
#include <cuda_runtime.h>
#include <float.h>
#include <math.h>

// Problem shape (fixed by dataset): B=4096, M=8192, K=32 neighbors.
#define BMAX  4096
#define TPB   256
#define NW    8
#define KNB   32
#define NBINS 256
#define CAP   512         // candidate capacity (expected ~60)
#define NEXT  34          // centrality extremes kept per end
#define CECAP 256

__device__ float g_centrality[BMAX];
__device__ float g_rowloss[BMAX];
__device__ float g_topv[NEXT]; __device__ int g_topi[NEXT];   // centrality top-34 desc
__device__ float g_botv[NEXT]; __device__ int g_boti[NEXT];   // centrality bot-34 asc
__device__ unsigned g_tick1 = 0u;   // centrality last-block ticket
__device__ unsigned g_tick2 = 0u;   // rowloss last-block ticket

// ---------------------------------------------------------------------------
// Kernel 1: centrality means; last CTA also computes global top/bot-34.
// ---------------------------------------------------------------------------
__global__ __launch_bounds__(TPB) void centrality_kernel(
    const float* __restrict__ mem, int B, int M)
{
    const int tid = threadIdx.x, lane = tid & 31, wid = tid >> 5;
    int row = blockIdx.x;
    {
        const float4* p = (const float4*)(mem + (size_t)row * M);
        // M = 8192 -> 2048 float4 -> exactly 8 per thread; fully batched loads.
        float4 v0 = p[tid + 0 * TPB];
        float4 v1 = p[tid + 1 * TPB];
        float4 v2 = p[tid + 2 * TPB];
        float4 v3 = p[tid + 3 * TPB];
        float4 v4 = p[tid + 4 * TPB];
        float4 v5 = p[tid + 5 * TPB];
        float4 v6 = p[tid + 6 * TPB];
        float4 v7 = p[tid + 7 * TPB];
        float s = (((v0.x + v0.y) + (v0.z + v0.w)) + ((v1.x + v1.y) + (v1.z + v1.w)))
                + (((v2.x + v2.y) + (v2.z + v2.w)) + ((v3.x + v3.y) + (v3.z + v3.w)))
                + (((v4.x + v4.y) + (v4.z + v4.w)) + ((v5.x + v5.y) + (v5.z + v5.w)))
                + (((v6.x + v6.y) + (v6.z + v6.w)) + ((v7.x + v7.y) + (v7.z + v7.w)));
        __shared__ float ws[NW];
        #pragma unroll
        for (int o = 16; o > 0; o >>= 1) s += __shfl_down_sync(0xffffffffu, s, o);
        if (lane == 0) ws[wid] = s;
        __syncthreads();
        if (tid < 32) {
            float t = (tid < NW) ? ws[tid] : 0.f;
            #pragma unroll
            for (int o = 4; o > 0; o >>= 1) t += __shfl_down_sync(0xffffffffu, t, o);
            if (tid == 0) g_centrality[row] = t / (float)M;
        }
    }

    // ---- last-CTA ticket: the final arriver computes centrality extremes ----
    __shared__ bool is_last;
    if (tid == 0) {
        __threadfence();
        unsigned o = atomicAdd(&g_tick1, 1u);
        is_last = (o == (unsigned)gridDim.x - 1u);
        if (is_last) g_tick1 = 0u;                 // reset for graph replay
    }
    __syncthreads();
    if (!is_last) return;
    __threadfence();                                // see all g_centrality writes

    __shared__ float    c[BMAX];
    __shared__ unsigned hist[NBINS];
    __shared__ float    tv[CECAP]; __shared__ int ti[CECAP];
    __shared__ float    bv[CECAP]; __shared__ int bi[CECAP];
    __shared__ float    wmn2[NW], wmx2[NW];
    __shared__ unsigned cntT, cntB;
    __shared__ int      sh_btop, sh_bbot;
    __shared__ float    sh_lo2, sh_scale2;

    float mn = FLT_MAX, mx = -FLT_MAX;
    #pragma unroll
    for (int k = 0; k < BMAX / TPB; k++) {
        float v = g_centrality[tid + k * TPB];
        c[tid + k * TPB] = v;
        mn = fminf(mn, v); mx = fmaxf(mx, v);
    }
    if (tid < NBINS) hist[tid] = 0u;
    if (tid == 0) { cntT = 0u; cntB = 0u; }
    #pragma unroll
    for (int o = 16; o > 0; o >>= 1) {
        mn = fminf(mn, __shfl_xor_sync(0xffffffffu, mn, o));
        mx = fmaxf(mx, __shfl_xor_sync(0xffffffffu, mx, o));
    }
    if (lane == 0) { wmn2[wid] = mn; wmx2[wid] = mx; }
    __syncthreads();
    if (tid == 0) {
        float lo = wmn2[0], hi = wmx2[0];
        #pragma unroll
        for (int w = 1; w < NW; w++) { lo = fminf(lo, wmn2[w]); hi = fmaxf(hi, wmx2[w]); }
        sh_lo2 = lo;
        sh_scale2 = (float)NBINS / fmaxf(hi - lo, 1e-30f);
    }
    __syncthreads();
    const float lo = sh_lo2, scale = sh_scale2;
    #pragma unroll
    for (int k = 0; k < BMAX / TPB; k++) {
        int b = (int)((c[tid + k * TPB] - lo) * scale);
        b = min(max(b, 0), NBINS - 1);
        atomicAdd(&hist[b], 1u);
    }
    __syncthreads();
    if (tid == 0) {
        unsigned cum = 0u; int b = NBINS - 1;
        for (; b >= 0; b--) { cum += hist[b]; if (cum >= NEXT) break; }
        sh_btop = b;
        cum = 0u; b = 0;
        for (; b < NBINS; b++) { cum += hist[b]; if (cum >= NEXT) break; }
        sh_bbot = b;
    }
    __syncthreads();
    const int btop = sh_btop, bbot = sh_bbot;
    #pragma unroll
    for (int k = 0; k < BMAX / TPB; k++) {
        int idx = tid + k * TPB;
        float v = c[idx];
        int b = (int)((v - lo) * scale);
        b = min(max(b, 0), NBINS - 1);
        if (b >= btop) { unsigned p = atomicAdd(&cntT, 1u); if (p < CECAP) { tv[p] = v; ti[p] = idx; } }
        if (b <= bbot) { unsigned p = atomicAdd(&cntB, 1u); if (p < CECAP) { bv[p] = v; bi[p] = idx; } }
    }
    __syncthreads();
    {
        int n = (int)min(cntT, (unsigned)CECAP);
        for (int q = tid; q < n; q += TPB) {
            float v = tv[q]; int id = ti[q]; int r = 0;
            for (int d = 0; d < n; d++) {
                float vd = tv[d];
                r += (vd > v) || (vd == v && ti[d] < id);
            }
            if (r < NEXT) { g_topv[r] = v; g_topi[r] = id; }
        }
        n = (int)min(cntB, (unsigned)CECAP);
        for (int q = tid; q < n; q += TPB) {
            float v = bv[q]; int id = bi[q]; int r = 0;
            for (int d = 0; d < n; d++) {
                float vd = bv[d];
                r += (vd < v) || (vd == v && bi[d] < id);
            }
            if (r < NEXT) { g_botv[r] = v; g_boti[r] = id; }
        }
    }
}

// ---------------------------------------------------------------------------
// Kernel 2: per-row loss, register-resident row (no shared row array).
//           Last CTA folds the deterministic mean into d_out.
// ---------------------------------------------------------------------------
__global__ __launch_bounds__(TPB) void rowloss_kernel(
    const float* __restrict__ sim, const float* __restrict__ temp_p,
    float* __restrict__ out, int B)
{
    __shared__ unsigned hist[NBINS];
    __shared__ float    cand_val[CAP];
    __shared__ int      cand_idx[CAP];
    __shared__ float    topval[KNB];
    __shared__ int      topidx[KNB];
    __shared__ int      exclidx[KNB + 1];
    __shared__ float    stv[NEXT]; __shared__ int sti[NEXT];
    __shared__ float    sbv[NEXT]; __shared__ int sbi[NEXT];
    __shared__ float    wmn[NW], wmx[NW];
    __shared__ unsigned sh_cnt;
    __shared__ int      sh_bstar;
    __shared__ float    sh_lo, sh_scale, sh_diag, sh_mxs;

    const int i    = blockIdx.x;
    const int tid  = threadIdx.x;
    const int wid  = tid >> 5;
    const int lane = tid & 31;

    // ---- load row into REGISTERS (16 floats/thread); stats on the fly ----
    float4 r0, r1, r2, r3;
    float mn = FLT_MAX, mx = -FLT_MAX, tm = -FLT_MAX;
    {
        const float4* rp = (const float4*)(sim + (size_t)i * B);
        const int dq = i >> 2, dl = i & 3;
        r0 = rp[tid];
        r1 = rp[tid + TPB];
        r2 = rp[tid + 2 * TPB];
        r3 = rp[tid + 3 * TPB];
        #pragma unroll
        for (int k = 0; k < 4; k++) {
            float4& v = (k == 0) ? r0 : (k == 1) ? r1 : (k == 2) ? r2 : r3;
            int j = tid + k * TPB;
            if (j == dq) {                          // strip diagonal from regs
                float dv = (dl == 0) ? v.x : (dl == 1) ? v.y : (dl == 2) ? v.z : v.w;
                sh_diag = dv;
                const float rep = (dl == 0) ? v.y : v.x;
                if (dl == 0) v.x = rep; else if (dl == 1) v.y = rep;
                else if (dl == 2) v.z = rep; else v.w = rep;
            }
            float lmx = fmaxf(fmaxf(v.x, v.y), fmaxf(v.z, v.w));
            mn = fminf(mn, fminf(fminf(v.x, v.y), fminf(v.z, v.w)));
            mx = fmaxf(mx, lmx);
            tm = fmaxf(tm, lmx);
        }
        if (tid < NBINS) hist[tid] = 0u;
        if (tid < NEXT) { stv[tid] = g_topv[tid]; sti[tid] = g_topi[tid];
                          sbv[tid] = g_botv[tid]; sbi[tid] = g_boti[tid]; }
        if (tid == 0) { sh_cnt = 0u; exclidx[KNB] = i; }
    }
    #pragma unroll
    for (int o = 16; o > 0; o >>= 1) {
        mn = fminf(mn, __shfl_xor_sync(0xffffffffu, mn, o));
        mx = fmaxf(mx, __shfl_xor_sync(0xffffffffu, mx, o));
    }
    if (lane == 0) { wmn[wid] = mn; wmx[wid] = mx; }
    __syncthreads();
    if (tid == 0) {
        float lo = wmn[0], hi = wmx[0];
        #pragma unroll
        for (int w = 1; w < NW; w++) { lo = fminf(lo, wmn[w]); hi = fmaxf(hi, wmx[w]); }
        sh_lo = lo;
        sh_scale = (float)NBINS / fmaxf(hi - lo, 1e-30f);
    }
    __syncthreads();

    const float lo = sh_lo, scale = sh_scale;

    // ---- histogram the 256 per-thread maxima (one atomic per thread) ----
    {
        int b = (int)((tm - lo) * scale);
        b = min(max(b, 0), NBINS - 1);
        atomicAdd(&hist[b], 1u);
    }
    __syncthreads();

    // ---- b* = bin of the 33rd-largest thread-max (warp-0 suffix scan) ----
    if (wid == 0) {
        unsigned running = 0u;
        int bstar = 0;
        bool found = false;
        for (int c = 0; c < NBINS / 32 && !found; c++) {
            int bin = NBINS - 1 - c * 32 - lane;
            unsigned p = hist[bin];
            #pragma unroll
            for (int o = 1; o < 32; o <<= 1) {
                unsigned t = __shfl_up_sync(0xffffffffu, p, o);
                if (lane >= o) p += t;
            }
            unsigned cum = running + p;
            unsigned ball = __ballot_sync(0xffffffffu, cum >= 33u);
            running += __shfl_sync(0xffffffffu, p, 31);
            if (ball) { bstar = NBINS - 1 - c * 32 - (__ffs(ball) - 1); found = true; }
        }
        if (lane == 0) sh_bstar = bstar;
    }
    __syncthreads();

    // ---- collect candidates (bin >= b*) straight from registers ----
    {
        const int bstar = sh_bstar;
        #pragma unroll
        for (int k = 0; k < 4; k++) {
            const float4 v = (k == 0) ? r0 : (k == 1) ? r1 : (k == 2) ? r2 : r3;
            int base = (tid + k * TPB) << 2;
            #pragma unroll
            for (int e = 0; e < 4; e++) {
                float f = (e == 0) ? v.x : (e == 1) ? v.y : (e == 2) ? v.z : v.w;
                int idx = base + e;
                int b = (int)((f - lo) * scale);
                b = min(max(b, 0), NBINS - 1);
                if (b >= bstar && idx != i) {
                    unsigned pos = atomicAdd(&sh_cnt, 1u);
                    if (pos < CAP) { cand_val[pos] = f; cand_idx[pos] = idx; }
                }
            }
        }
    }
    __syncthreads();

    // ---- exact rank by counting (ties: lower index first, matches top_k) ----
    {
        int n = (int)min(sh_cnt, (unsigned)CAP);
        for (int c = tid; c < n; c += TPB) {
            float v = cand_val[c];
            int   id = cand_idx[c];
            int r = 0;
            for (int d = 0; d < n; d++) {
                float vd = cand_val[d];
                r += (vd > v) || (vd == v && cand_idx[d] < id);
            }
            if (r < KNB) {
                topval[r] = v;
                topidx[r] = id;
                exclidx[r] = id;
            } else if (r == KNB) {
                sh_mxs = v;                        // mx_s = 33rd largest off-diag
            }
        }
    }
    __syncthreads();

    // ---- warp 0: centrality extremes via global 34-lists, then epilogue ----
    if (tid < 32) {
        const int ex = (lane <= KNB) ? exclidx[lane] : -1;   // 33 excluded ids
        float mx_c = stv[NEXT - 1];
        #pragma unroll 4
        for (int e = 0; e < NEXT; e++) {
            int id = sti[e];
            if (!__ballot_sync(0xffffffffu, ex == id)) { mx_c = stv[e]; break; }
        }
        float mn_c = sbv[NEXT - 1];
        #pragma unroll 4
        for (int e = 0; e < NEXT; e++) {
            int id = sbi[e];
            if (!__ballot_sync(0xffffffffu, ex == id)) { mn_c = sbv[e]; break; }
        }
        const float mn_s = sh_lo, mx_s = sh_mxs;

        float tv2 = topval[lane];
        int   ti2 = topidx[lane];
        float dg  = sh_diag;

        // logsumexp over extended set (32 neighbors + diagonal)
        float m = tv2;
        #pragma unroll
        for (int o = 16; o > 0; o >>= 1) m = fmaxf(m, __shfl_xor_sync(0xffffffffu, m, o));
        m = fmaxf(m, dg);
        float s = expf(tv2 - m);
        #pragma unroll
        for (int o = 16; o > 0; o >>= 1) s += __shfl_xor_sync(0xffffffffu, s, o);
        s += expf(dg - m);
        float lse = logf(s) + m;

        // positive weights: softmax over neighbors of (norm_sim - norm_cent)*T
        float T  = *temp_p;
        float ns = (tv2 - mn_s) / (mx_s - mn_s);
        float nc = (g_centrality[ti2] - mn_c) / (mx_c - mn_c);
        float a  = (ns - nc) * T;
        float am = a;
        #pragma unroll
        for (int o = 16; o > 0; o >>= 1) am = fmaxf(am, __shfl_xor_sync(0xffffffffu, am, o));
        float pe = expf(a - am);
        float ps = pe;
        #pragma unroll
        for (int o = 16; o > 0; o >>= 1) ps += __shfl_xor_sync(0xffffffffu, ps, o);
        float pw = pe / ps;

        float num   = pw * (tv2 - lse);
        float pwsum = pw;
        #pragma unroll
        for (int o = 16; o > 0; o >>= 1) {
            num   += __shfl_xor_sync(0xffffffffu, num,   o);
            pwsum += __shfl_xor_sync(0xffffffffu, pwsum, o);
        }
        if (lane == 0) {
            float numer = num + (dg - lse);
            float denom = pwsum + 1.0f;
            g_rowloss[i] = -numer / denom;
        }
    }

    // ---- last-CTA ticket: deterministic mean into d_out ----
    __shared__ bool is_last;
    if (tid == 0) {
        __threadfence();                            // publish g_rowloss[i]
        unsigned o = atomicAdd(&g_tick2, 1u);
        is_last = (o == (unsigned)gridDim.x - 1u);
        if (is_last) g_tick2 = 0u;                  // reset for graph replay
    }
    __syncthreads();
    if (!is_last) return;
    __threadfence();                                // see all rows

    double s = 0.0;
    #pragma unroll
    for (int k = 0; k < BMAX / TPB; k++) s += (double)g_rowloss[tid + k * TPB];
    __shared__ double wsd[NW];
    #pragma unroll
    for (int o = 16; o > 0; o >>= 1) s += __shfl_down_sync(0xffffffffu, s, o);
    if (lane == 0) wsd[wid] = s;
    __syncthreads();
    if (tid < 32) {
        double t = (tid < NW) ? wsd[tid] : 0.0;
        #pragma unroll
        for (int o = 4; o > 0; o >>= 1) t += __shfl_down_sync(0xffffffffu, t, o);
        if (tid == 0) out[0] = (float)(t / (double)B);
    }
}

// ---------------------------------------------------------------------------
extern "C" void kernel_launch(void* const* d_in, const int* in_sizes, int n_in,
                              void* d_out, int out_size)
{
    const float* sim  = (const float*)d_in[0];
    const float* mem  = (const float*)d_in[1];
    const float* temp = (const float*)d_in[n_in - 1];

    int nsim = in_sizes[0];
    int B = 1;
    while ((long long)B * B < (long long)nsim) B <<= 1;   // B = 4096
    int M = in_sizes[1] / B;                               // M = 8192

    centrality_kernel<<<B, TPB>>>(mem, B, M);
    rowloss_kernel<<<B, TPB>>>(sim, temp, (float*)d_out, B);
}

// round 7
// speedup vs baseline: 1.0953x; 1.0953x over previous
#include <cuda_runtime.h>
#include <float.h>
#include <math.h>

// Problem shape (fixed by dataset): B=4096, M=8192, K=32 neighbors.
#define BMAX  4096
#define TPB   256
#define NW    8
#define KNB   32
#define NBINS 256
#define CAP   512         // candidate capacity (expected ~60)
#define NEXT  34          // centrality extremes kept per end
#define CECAP 256

__device__ float g_centrality[BMAX];
__device__ float g_rowloss[BMAX];
__device__ float g_topv[NEXT]; __device__ int g_topi[NEXT];   // centrality top-34 desc
__device__ float g_botv[NEXT]; __device__ int g_boti[NEXT];   // centrality bot-34 asc
__device__ unsigned g_tick = 0u;    // rowloss last-block ticket

// ---------------------------------------------------------------------------
// Kernel 1: centrality[row] = mean(memory_bank[row, :])  (R5 form, measured)
// ---------------------------------------------------------------------------
__global__ __launch_bounds__(TPB) void centrality_kernel(
    const float* __restrict__ mem, int B, int M)
{
    int row = blockIdx.x;
    const float4* p = (const float4*)(mem + (size_t)row * M);
    float4 v0 = p[threadIdx.x + 0 * TPB];
    float4 v1 = p[threadIdx.x + 1 * TPB];
    float4 v2 = p[threadIdx.x + 2 * TPB];
    float4 v3 = p[threadIdx.x + 3 * TPB];
    float4 v4 = p[threadIdx.x + 4 * TPB];
    float4 v5 = p[threadIdx.x + 5 * TPB];
    float4 v6 = p[threadIdx.x + 6 * TPB];
    float4 v7 = p[threadIdx.x + 7 * TPB];
    float s = (((v0.x + v0.y) + (v0.z + v0.w)) + ((v1.x + v1.y) + (v1.z + v1.w)))
            + (((v2.x + v2.y) + (v2.z + v2.w)) + ((v3.x + v3.y) + (v3.z + v3.w)))
            + (((v4.x + v4.y) + (v4.z + v4.w)) + ((v5.x + v5.y) + (v5.z + v5.w)))
            + (((v6.x + v6.y) + (v6.z + v6.w)) + ((v7.x + v7.y) + (v7.z + v7.w)));
    __shared__ float ws[NW];
    #pragma unroll
    for (int o = 16; o > 0; o >>= 1) s += __shfl_down_sync(0xffffffffu, s, o);
    if ((threadIdx.x & 31) == 0) ws[threadIdx.x >> 5] = s;
    __syncthreads();
    if (threadIdx.x < 32) {
        float t = (threadIdx.x < NW) ? ws[threadIdx.x] : 0.f;
        #pragma unroll
        for (int o = 4; o > 0; o >>= 1) t += __shfl_down_sync(0xffffffffu, t, o);
        if (threadIdx.x == 0) g_centrality[row] = t / (float)M;
    }
}

// ---------------------------------------------------------------------------
// Kernel 1b: global top-34 / bottom-34 of centrality (one CTA, one-off).
// ---------------------------------------------------------------------------
__global__ __launch_bounds__(TPB) void cextremes_kernel()
{
    __shared__ float    c[BMAX];
    __shared__ unsigned hist[NBINS];
    __shared__ float    tv[CECAP]; __shared__ int ti[CECAP];
    __shared__ float    bv[CECAP]; __shared__ int bi[CECAP];
    __shared__ float    wmn[NW], wmx[NW];
    __shared__ unsigned cntT, cntB;
    __shared__ int      sh_btop, sh_bbot;
    __shared__ float    sh_lo, sh_scale;

    const int tid = threadIdx.x, lane = tid & 31, wid = tid >> 5;
    float mn = FLT_MAX, mx = -FLT_MAX;
    #pragma unroll
    for (int k = 0; k < BMAX / TPB; k++) {
        float v = g_centrality[tid + k * TPB];
        c[tid + k * TPB] = v;
        mn = fminf(mn, v); mx = fmaxf(mx, v);
    }
    if (tid < NBINS) hist[tid] = 0u;
    if (tid == 0) { cntT = 0u; cntB = 0u; }
    #pragma unroll
    for (int o = 16; o > 0; o >>= 1) {
        mn = fminf(mn, __shfl_xor_sync(0xffffffffu, mn, o));
        mx = fmaxf(mx, __shfl_xor_sync(0xffffffffu, mx, o));
    }
    if (lane == 0) { wmn[wid] = mn; wmx[wid] = mx; }
    __syncthreads();
    if (tid == 0) {
        float lo = wmn[0], hi = wmx[0];
        #pragma unroll
        for (int w = 1; w < NW; w++) { lo = fminf(lo, wmn[w]); hi = fmaxf(hi, wmx[w]); }
        sh_lo = lo;
        sh_scale = (float)NBINS / fmaxf(hi - lo, 1e-30f);
    }
    __syncthreads();
    const float lo = sh_lo, scale = sh_scale;
    #pragma unroll
    for (int k = 0; k < BMAX / TPB; k++) {
        int b = (int)((c[tid + k * TPB] - lo) * scale);
        b = min(max(b, 0), NBINS - 1);
        atomicAdd(&hist[b], 1u);
    }
    __syncthreads();
    if (tid == 0) {
        unsigned cum = 0u; int b = NBINS - 1;
        for (; b >= 0; b--) { cum += hist[b]; if (cum >= NEXT) break; }
        sh_btop = b;
        cum = 0u; b = 0;
        for (; b < NBINS; b++) { cum += hist[b]; if (cum >= NEXT) break; }
        sh_bbot = b;
    }
    __syncthreads();
    const int btop = sh_btop, bbot = sh_bbot;
    #pragma unroll
    for (int k = 0; k < BMAX / TPB; k++) {
        int idx = tid + k * TPB;
        float v = c[idx];
        int b = (int)((v - lo) * scale);
        b = min(max(b, 0), NBINS - 1);
        if (b >= btop) { unsigned p = atomicAdd(&cntT, 1u); if (p < CECAP) { tv[p] = v; ti[p] = idx; } }
        if (b <= bbot) { unsigned p = atomicAdd(&cntB, 1u); if (p < CECAP) { bv[p] = v; bi[p] = idx; } }
    }
    __syncthreads();
    {
        int n = (int)min(cntT, (unsigned)CECAP);
        for (int q = tid; q < n; q += TPB) {
            float v = tv[q]; int id = ti[q]; int r = 0;
            for (int d = 0; d < n; d++) {
                float vd = tv[d];
                r += (vd > v) || (vd == v && ti[d] < id);
            }
            if (r < NEXT) { g_topv[r] = v; g_topi[r] = id; }
        }
        n = (int)min(cntB, (unsigned)CECAP);
        for (int q = tid; q < n; q += TPB) {
            float v = bv[q]; int id = bi[q]; int r = 0;
            for (int d = 0; d < n; d++) {
                float vd = bv[d];
                r += (vd < v) || (vd == v && bi[d] < id);
            }
            if (r < NEXT) { g_botv[r] = v; g_boti[r] = id; }
        }
    }
}

// ---------------------------------------------------------------------------
// Kernel 2: per-row loss, smem-resident row + thread-max prefilter.
//           Last CTA folds the deterministic mean into d_out.
// ---------------------------------------------------------------------------
__global__ __launch_bounds__(TPB) void rowloss_kernel(
    const float* __restrict__ sim, const float* __restrict__ temp_p,
    float* __restrict__ out, int B)
{
    __shared__ float    srow[BMAX];
    __shared__ unsigned hist[NBINS];
    __shared__ float    cand_val[CAP];
    __shared__ int      cand_idx[CAP];
    __shared__ float    topval[KNB];
    __shared__ int      topidx[KNB];
    __shared__ int      exclidx[KNB + 1];
    __shared__ float    stv[NEXT]; __shared__ int sti[NEXT];
    __shared__ float    sbv[NEXT]; __shared__ int sbi[NEXT];
    __shared__ float    wmn[NW], wmx[NW];
    __shared__ unsigned sh_cnt;
    __shared__ float    sh_thr;
    __shared__ float    sh_lo, sh_scale, sh_diag, sh_mxs;

    const int i    = blockIdx.x;
    const int tid  = threadIdx.x;
    const int wid  = tid >> 5;
    const int lane = tid & 31;

    // ---- load row -> smem; per-thread min/max/threadmax (diag excluded) ----
    float mn = FLT_MAX, mx = -FLT_MAX, tm = -FLT_MAX;
    {
        const float4* rp = (const float4*)(sim + (size_t)i * B);
        const int dq = i >> 2, dl = i & 3;
        #pragma unroll
        for (int k = 0; k < 4; k++) {
            int j = tid + k * TPB;
            float4 v = rp[j];
            if (j == dq) {                          // strip diagonal
                float dv = (dl == 0) ? v.x : (dl == 1) ? v.y : (dl == 2) ? v.z : v.w;
                sh_diag = dv;
                const float rep = (dl == 0) ? v.y : v.x;
                if (dl == 0) v.x = rep; else if (dl == 1) v.y = rep;
                else if (dl == 2) v.z = rep; else v.w = rep;
            }
            ((float4*)srow)[j] = v;                 // diag-stripped copy
            float lmx = fmaxf(fmaxf(v.x, v.y), fmaxf(v.z, v.w));
            mn = fminf(mn, fminf(fminf(v.x, v.y), fminf(v.z, v.w)));
            mx = fmaxf(mx, lmx);
            tm = fmaxf(tm, lmx);
        }
        if (tid < NBINS) hist[tid] = 0u;
        if (tid < NEXT) { stv[tid] = g_topv[tid]; sti[tid] = g_topi[tid];
                          sbv[tid] = g_botv[tid]; sbi[tid] = g_boti[tid]; }
        if (tid == 0) { sh_cnt = 0u; exclidx[KNB] = i; }
    }
    #pragma unroll
    for (int o = 16; o > 0; o >>= 1) {
        mn = fminf(mn, __shfl_xor_sync(0xffffffffu, mn, o));
        mx = fmaxf(mx, __shfl_xor_sync(0xffffffffu, mx, o));
    }
    if (lane == 0) { wmn[wid] = mn; wmx[wid] = mx; }
    __syncthreads();
    if (tid == 0) {
        float lo = wmn[0], hi = wmx[0];
        #pragma unroll
        for (int w = 1; w < NW; w++) { lo = fminf(lo, wmn[w]); hi = fmaxf(hi, wmx[w]); }
        sh_lo = lo;
        sh_scale = (float)NBINS / fmaxf(hi - lo, 1e-30f);
    }
    __syncthreads();

    const float lo = sh_lo, scale = sh_scale;

    // ---- histogram the 256 per-thread maxima (one atomic per thread) ----
    {
        int b = (int)((tm - lo) * scale);
        b = min(max(b, 0), NBINS - 1);
        atomicAdd(&hist[b], 1u);
    }
    __syncthreads();

    // ---- b* = bin of the 33rd-largest thread-max; publish as float thresh:
    //      bin(v) >= b*  <=>  (v-lo)*scale >= (float)b*  (operand >= 0) ----
    if (wid == 0) {
        unsigned running = 0u;
        bool found = false;
        for (int c = 0; c < NBINS / 32 && !found; c++) {
            int bin = NBINS - 1 - c * 32 - lane;
            unsigned p = hist[bin];
            #pragma unroll
            for (int o = 1; o < 32; o <<= 1) {
                unsigned t = __shfl_up_sync(0xffffffffu, p, o);
                if (lane >= o) p += t;
            }
            unsigned cum = running + p;
            unsigned ball = __ballot_sync(0xffffffffu, cum >= 33u);
            running += __shfl_sync(0xffffffffu, p, 31);
            if (ball) {
                int bstar = NBINS - 1 - c * 32 - (__ffs(ball) - 1);
                if (lane == 0) sh_thr = (float)bstar;
                found = true;
            }
        }
    }
    __syncthreads();

    // ---- collect candidates: one FMA + compare per element (no F2I) ----
    {
        const float thr = sh_thr;
        #pragma unroll
        for (int k = 0; k < 4; k++) {
            int j = tid + k * TPB;
            float4 v = ((const float4*)srow)[j];
            int base = j << 2;
            #pragma unroll
            for (int e = 0; e < 4; e++) {
                float f = (e == 0) ? v.x : (e == 1) ? v.y : (e == 2) ? v.z : v.w;
                if ((f - lo) * scale >= thr) {
                    int idx = base + e;
                    if (idx != i) {
                        unsigned pos = atomicAdd(&sh_cnt, 1u);
                        if (pos < CAP) { cand_val[pos] = f; cand_idx[pos] = idx; }
                    }
                }
            }
        }
    }
    __syncthreads();

    // ---- exact rank by counting (ties: lower index first, matches top_k) ----
    {
        int n = (int)min(sh_cnt, (unsigned)CAP);
        for (int c = tid; c < n; c += TPB) {
            float v = cand_val[c];
            int   id = cand_idx[c];
            int r = 0;
            for (int d = 0; d < n; d++) {
                float vd = cand_val[d];
                r += (vd > v) || (vd == v && cand_idx[d] < id);
            }
            if (r < KNB) {
                topval[r] = v;
                topidx[r] = id;
                exclidx[r] = id;
            } else if (r == KNB) {
                sh_mxs = v;                        // mx_s = 33rd largest off-diag
            }
        }
    }
    __syncthreads();

    // ---- warp 0: centrality extremes via global 34-lists, then epilogue ----
    if (tid < 32) {
        const int ex = (lane <= KNB) ? exclidx[lane] : -1;   // 33 excluded ids
        float mx_c = stv[NEXT - 1];
        #pragma unroll 4
        for (int e = 0; e < NEXT; e++) {
            int id = sti[e];
            if (!__ballot_sync(0xffffffffu, ex == id)) { mx_c = stv[e]; break; }
        }
        float mn_c = sbv[NEXT - 1];
        #pragma unroll 4
        for (int e = 0; e < NEXT; e++) {
            int id = sbi[e];
            if (!__ballot_sync(0xffffffffu, ex == id)) { mn_c = sbv[e]; break; }
        }
        const float mn_s = sh_lo, mx_s = sh_mxs;

        float tv2 = topval[lane];
        int   ti2 = topidx[lane];
        float dg  = sh_diag;

        // logsumexp over extended set (32 neighbors + diagonal)
        float m = tv2;
        #pragma unroll
        for (int o = 16; o > 0; o >>= 1) m = fmaxf(m, __shfl_xor_sync(0xffffffffu, m, o));
        m = fmaxf(m, dg);
        float s = expf(tv2 - m);
        #pragma unroll
        for (int o = 16; o > 0; o >>= 1) s += __shfl_xor_sync(0xffffffffu, s, o);
        s += expf(dg - m);
        float lse = logf(s) + m;

        // positive weights: softmax over neighbors of (norm_sim - norm_cent)*T
        float T  = *temp_p;
        float ns = (tv2 - mn_s) / (mx_s - mn_s);
        float nc = (g_centrality[ti2] - mn_c) / (mx_c - mn_c);
        float a  = (ns - nc) * T;
        float am = a;
        #pragma unroll
        for (int o = 16; o > 0; o >>= 1) am = fmaxf(am, __shfl_xor_sync(0xffffffffu, am, o));
        float pe = expf(a - am);
        float ps = pe;
        #pragma unroll
        for (int o = 16; o > 0; o >>= 1) ps += __shfl_xor_sync(0xffffffffu, ps, o);
        float pw = pe / ps;

        float num   = pw * (tv2 - lse);
        float pwsum = pw;
        #pragma unroll
        for (int o = 16; o > 0; o >>= 1) {
            num   += __shfl_xor_sync(0xffffffffu, num,   o);
            pwsum += __shfl_xor_sync(0xffffffffu, pwsum, o);
        }
        if (lane == 0) {
            float numer = num + (dg - lse);
            float denom = pwsum + 1.0f;
            g_rowloss[i] = -numer / denom;
        }
    }

    // ---- last-CTA ticket: deterministic mean into d_out (no extra smem) ----
    __shared__ bool is_last;
    if (tid == 0) {
        __threadfence();                            // publish g_rowloss[i]
        unsigned o = atomicAdd(&g_tick, 1u);
        is_last = (o == (unsigned)gridDim.x - 1u);
        if (is_last) g_tick = 0u;                   // reset for graph replay
    }
    __syncthreads();
    if (!is_last) return;
    __threadfence();                                // see all rows

    double s = 0.0;
    #pragma unroll
    for (int k = 0; k < BMAX / TPB; k++) s += (double)g_rowloss[tid + k * TPB];
    __shared__ double wsd[NW];
    #pragma unroll
    for (int o = 16; o > 0; o >>= 1) s += __shfl_down_sync(0xffffffffu, s, o);
    if (lane == 0) wsd[wid] = s;
    __syncthreads();
    if (tid < 32) {
        double t = (tid < NW) ? wsd[tid] : 0.0;
        #pragma unroll
        for (int o = 4; o > 0; o >>= 1) t += __shfl_down_sync(0xffffffffu, t, o);
        if (tid == 0) out[0] = (float)(t / (double)B);
    }
}

// ---------------------------------------------------------------------------
extern "C" void kernel_launch(void* const* d_in, const int* in_sizes, int n_in,
                              void* d_out, int out_size)
{
    const float* sim  = (const float*)d_in[0];
    const float* mem  = (const float*)d_in[1];
    const float* temp = (const float*)d_in[n_in - 1];

    int nsim = in_sizes[0];
    int B = 1;
    while ((long long)B * B < (long long)nsim) B <<= 1;   // B = 4096
    int M = in_sizes[1] / B;                               // M = 8192

    centrality_kernel<<<B, TPB>>>(mem, B, M);
    cextremes_kernel<<<1, TPB>>>();
    rowloss_kernel<<<B, TPB>>>(sim, temp, (float*)d_out, B);
}

// round 8
// speedup vs baseline: 1.2136x; 1.1080x over previous
#include <cuda_runtime.h>
#include <float.h>
#include <math.h>

// Problem shape (fixed by dataset): B=4096, M=8192, K=32 neighbors.
#define BMAX  4096
#define TPB   256
#define NW    8
#define KNB   32
#define NBINS 256
#define CAP   512         // candidate capacity (expected ~60)
#define NEXT  34          // centrality extremes kept per end
#define CECAP 256
#define TPR   512         // reduce kernel threads

__device__ float g_centrality[BMAX];
__device__ float g_rowloss[BMAX];
__device__ float g_topv[NEXT]; __device__ int g_topi[NEXT];   // centrality top-34 desc
__device__ float g_botv[NEXT]; __device__ int g_boti[NEXT];   // centrality bot-34 asc

// ---------------------------------------------------------------------------
// Kernel 1: centrality[row] = mean(memory_bank[row, :])  (R5 form, measured)
// ---------------------------------------------------------------------------
__global__ __launch_bounds__(TPB) void centrality_kernel(
    const float* __restrict__ mem, int B, int M)
{
    int row = blockIdx.x;
    const float4* p = (const float4*)(mem + (size_t)row * M);
    float4 v0 = p[threadIdx.x + 0 * TPB];
    float4 v1 = p[threadIdx.x + 1 * TPB];
    float4 v2 = p[threadIdx.x + 2 * TPB];
    float4 v3 = p[threadIdx.x + 3 * TPB];
    float4 v4 = p[threadIdx.x + 4 * TPB];
    float4 v5 = p[threadIdx.x + 5 * TPB];
    float4 v6 = p[threadIdx.x + 6 * TPB];
    float4 v7 = p[threadIdx.x + 7 * TPB];
    float s = (((v0.x + v0.y) + (v0.z + v0.w)) + ((v1.x + v1.y) + (v1.z + v1.w)))
            + (((v2.x + v2.y) + (v2.z + v2.w)) + ((v3.x + v3.y) + (v3.z + v3.w)))
            + (((v4.x + v4.y) + (v4.z + v4.w)) + ((v5.x + v5.y) + (v5.z + v5.w)))
            + (((v6.x + v6.y) + (v6.z + v6.w)) + ((v7.x + v7.y) + (v7.z + v7.w)));
    __shared__ float ws[NW];
    #pragma unroll
    for (int o = 16; o > 0; o >>= 1) s += __shfl_down_sync(0xffffffffu, s, o);
    if ((threadIdx.x & 31) == 0) ws[threadIdx.x >> 5] = s;
    __syncthreads();
    if (threadIdx.x < 32) {
        float t = (threadIdx.x < NW) ? ws[threadIdx.x] : 0.f;
        #pragma unroll
        for (int o = 4; o > 0; o >>= 1) t += __shfl_down_sync(0xffffffffu, t, o);
        if (threadIdx.x == 0) g_centrality[row] = t / (float)M;
    }
}

// ---------------------------------------------------------------------------
// Kernel 1b: global top-34 / bottom-34 of centrality (one CTA, one-off).
// ---------------------------------------------------------------------------
__global__ __launch_bounds__(TPB) void cextremes_kernel()
{
    __shared__ float    c[BMAX];
    __shared__ unsigned hist[NBINS];
    __shared__ float    tv[CECAP]; __shared__ int ti[CECAP];
    __shared__ float    bv[CECAP]; __shared__ int bi[CECAP];
    __shared__ float    wmn[NW], wmx[NW];
    __shared__ unsigned cntT, cntB;
    __shared__ int      sh_btop, sh_bbot;
    __shared__ float    sh_lo, sh_scale;

    const int tid = threadIdx.x, lane = tid & 31, wid = tid >> 5;
    float mn = FLT_MAX, mx = -FLT_MAX;
    #pragma unroll
    for (int k = 0; k < BMAX / TPB; k++) {
        float v = g_centrality[tid + k * TPB];
        c[tid + k * TPB] = v;
        mn = fminf(mn, v); mx = fmaxf(mx, v);
    }
    if (tid < NBINS) hist[tid] = 0u;
    if (tid == 0) { cntT = 0u; cntB = 0u; }
    #pragma unroll
    for (int o = 16; o > 0; o >>= 1) {
        mn = fminf(mn, __shfl_xor_sync(0xffffffffu, mn, o));
        mx = fmaxf(mx, __shfl_xor_sync(0xffffffffu, mx, o));
    }
    if (lane == 0) { wmn[wid] = mn; wmx[wid] = mx; }
    __syncthreads();
    if (tid == 0) {
        float lo = wmn[0], hi = wmx[0];
        #pragma unroll
        for (int w = 1; w < NW; w++) { lo = fminf(lo, wmn[w]); hi = fmaxf(hi, wmx[w]); }
        sh_lo = lo;
        sh_scale = (float)NBINS / fmaxf(hi - lo, 1e-30f);
    }
    __syncthreads();
    const float lo = sh_lo, scale = sh_scale;
    #pragma unroll
    for (int k = 0; k < BMAX / TPB; k++) {
        int b = (int)((c[tid + k * TPB] - lo) * scale);
        b = min(max(b, 0), NBINS - 1);
        atomicAdd(&hist[b], 1u);
    }
    __syncthreads();
    if (tid == 0) {
        unsigned cum = 0u; int b = NBINS - 1;
        for (; b >= 0; b--) { cum += hist[b]; if (cum >= NEXT) break; }
        sh_btop = b;
        cum = 0u; b = 0;
        for (; b < NBINS; b++) { cum += hist[b]; if (cum >= NEXT) break; }
        sh_bbot = b;
    }
    __syncthreads();
    const int btop = sh_btop, bbot = sh_bbot;
    #pragma unroll
    for (int k = 0; k < BMAX / TPB; k++) {
        int idx = tid + k * TPB;
        float v = c[idx];
        int b = (int)((v - lo) * scale);
        b = min(max(b, 0), NBINS - 1);
        if (b >= btop) { unsigned p = atomicAdd(&cntT, 1u); if (p < CECAP) { tv[p] = v; ti[p] = idx; } }
        if (b <= bbot) { unsigned p = atomicAdd(&cntB, 1u); if (p < CECAP) { bv[p] = v; bi[p] = idx; } }
    }
    __syncthreads();
    {
        int n = (int)min(cntT, (unsigned)CECAP);
        for (int q = tid; q < n; q += TPB) {
            float v = tv[q]; int id = ti[q]; int r = 0;
            for (int d = 0; d < n; d++) {
                float vd = tv[d];
                r += (vd > v) || (vd == v && ti[d] < id);
            }
            if (r < NEXT) { g_topv[r] = v; g_topi[r] = id; }
        }
        n = (int)min(cntB, (unsigned)CECAP);
        for (int q = tid; q < n; q += TPB) {
            float v = bv[q]; int id = bi[q]; int r = 0;
            for (int d = 0; d < n; d++) {
                float vd = bv[d];
                r += (vd < v) || (vd == v && bi[d] < id);
            }
            if (r < NEXT) { g_botv[r] = v; g_boti[r] = id; }
        }
    }
}

// ---------------------------------------------------------------------------
// Kernel 2: per-row loss, smem-resident row + thread-max prefilter.
//           (R5 structure: NO fence, NO fused tail.)
// ---------------------------------------------------------------------------
__global__ __launch_bounds__(TPB) void rowloss_kernel(
    const float* __restrict__ sim, const float* __restrict__ temp_p, int B)
{
    __shared__ float    srow[BMAX];
    __shared__ unsigned hist[NBINS];
    __shared__ float    cand_val[CAP];
    __shared__ int      cand_idx[CAP];
    __shared__ float    topval[KNB];
    __shared__ int      topidx[KNB];
    __shared__ int      exclidx[KNB + 1];
    __shared__ float    stv[NEXT]; __shared__ int sti[NEXT];
    __shared__ float    sbv[NEXT]; __shared__ int sbi[NEXT];
    __shared__ float    wmn[NW], wmx[NW];
    __shared__ unsigned sh_cnt;
    __shared__ float    sh_thr;
    __shared__ float    sh_lo, sh_scale, sh_diag, sh_mxs;

    const int i    = blockIdx.x;
    const int tid  = threadIdx.x;
    const int wid  = tid >> 5;
    const int lane = tid & 31;

    // ---- load row -> smem; per-thread min/max/threadmax (diag excluded) ----
    float mn = FLT_MAX, mx = -FLT_MAX, tm = -FLT_MAX;
    {
        const float4* rp = (const float4*)(sim + (size_t)i * B);
        const int dq = i >> 2, dl = i & 3;
        #pragma unroll
        for (int k = 0; k < 4; k++) {
            int j = tid + k * TPB;
            float4 v = rp[j];
            if (j == dq) {                          // strip diagonal
                float dv = (dl == 0) ? v.x : (dl == 1) ? v.y : (dl == 2) ? v.z : v.w;
                sh_diag = dv;
                const float rep = (dl == 0) ? v.y : v.x;
                if (dl == 0) v.x = rep; else if (dl == 1) v.y = rep;
                else if (dl == 2) v.z = rep; else v.w = rep;
            }
            ((float4*)srow)[j] = v;                 // diag-stripped copy
            float lmx = fmaxf(fmaxf(v.x, v.y), fmaxf(v.z, v.w));
            mn = fminf(mn, fminf(fminf(v.x, v.y), fminf(v.z, v.w)));
            mx = fmaxf(mx, lmx);
            tm = fmaxf(tm, lmx);
        }
        if (tid < NBINS) hist[tid] = 0u;
        if (tid < NEXT) { stv[tid] = g_topv[tid]; sti[tid] = g_topi[tid];
                          sbv[tid] = g_botv[tid]; sbi[tid] = g_boti[tid]; }
        if (tid == 0) { sh_cnt = 0u; exclidx[KNB] = i; }
    }
    #pragma unroll
    for (int o = 16; o > 0; o >>= 1) {
        mn = fminf(mn, __shfl_xor_sync(0xffffffffu, mn, o));
        mx = fmaxf(mx, __shfl_xor_sync(0xffffffffu, mx, o));
    }
    if (lane == 0) { wmn[wid] = mn; wmx[wid] = mx; }
    __syncthreads();
    if (tid == 0) {
        float lo = wmn[0], hi = wmx[0];
        #pragma unroll
        for (int w = 1; w < NW; w++) { lo = fminf(lo, wmn[w]); hi = fmaxf(hi, wmx[w]); }
        sh_lo = lo;
        sh_scale = (float)NBINS / fmaxf(hi - lo, 1e-30f);
    }
    __syncthreads();

    const float lo = sh_lo, scale = sh_scale;

    // ---- histogram the 256 per-thread maxima (one atomic per thread) ----
    {
        int b = (int)((tm - lo) * scale);
        b = min(max(b, 0), NBINS - 1);
        atomicAdd(&hist[b], 1u);
    }
    __syncthreads();

    // ---- b* = bin of the 33rd-largest thread-max; publish as float thresh:
    //      bin(v) >= b*  <=>  (v-lo)*scale >= (float)b*  (operand >= 0) ----
    if (wid == 0) {
        unsigned running = 0u;
        bool found = false;
        for (int c = 0; c < NBINS / 32 && !found; c++) {
            int bin = NBINS - 1 - c * 32 - lane;
            unsigned p = hist[bin];
            #pragma unroll
            for (int o = 1; o < 32; o <<= 1) {
                unsigned t = __shfl_up_sync(0xffffffffu, p, o);
                if (lane >= o) p += t;
            }
            unsigned cum = running + p;
            unsigned ball = __ballot_sync(0xffffffffu, cum >= 33u);
            running += __shfl_sync(0xffffffffu, p, 31);
            if (ball) {
                int bstar = NBINS - 1 - c * 32 - (__ffs(ball) - 1);
                if (lane == 0) sh_thr = (float)bstar;
                found = true;
            }
        }
    }
    __syncthreads();

    // ---- collect candidates: one FMA + compare per element (no F2I) ----
    {
        const float thr = sh_thr;
        #pragma unroll
        for (int k = 0; k < 4; k++) {
            int j = tid + k * TPB;
            float4 v = ((const float4*)srow)[j];
            int base = j << 2;
            #pragma unroll
            for (int e = 0; e < 4; e++) {
                float f = (e == 0) ? v.x : (e == 1) ? v.y : (e == 2) ? v.z : v.w;
                if ((f - lo) * scale >= thr) {
                    int idx = base + e;
                    if (idx != i) {
                        unsigned pos = atomicAdd(&sh_cnt, 1u);
                        if (pos < CAP) { cand_val[pos] = f; cand_idx[pos] = idx; }
                    }
                }
            }
        }
    }
    __syncthreads();

    // ---- exact rank by counting (ties: lower index first, matches top_k) ----
    {
        int n = (int)min(sh_cnt, (unsigned)CAP);
        for (int c = tid; c < n; c += TPB) {
            float v = cand_val[c];
            int   id = cand_idx[c];
            int r = 0;
            for (int d = 0; d < n; d++) {
                float vd = cand_val[d];
                r += (vd > v) || (vd == v && cand_idx[d] < id);
            }
            if (r < KNB) {
                topval[r] = v;
                topidx[r] = id;
                exclidx[r] = id;
            } else if (r == KNB) {
                sh_mxs = v;                        // mx_s = 33rd largest off-diag
            }
        }
    }
    __syncthreads();

    // ---- warp 0: centrality extremes via global 34-lists, then epilogue ----
    if (tid < 32) {
        const int ex = (lane <= KNB) ? exclidx[lane] : -1;   // 33 excluded ids
        float mx_c = stv[NEXT - 1];
        #pragma unroll 4
        for (int e = 0; e < NEXT; e++) {
            int id = sti[e];
            if (!__ballot_sync(0xffffffffu, ex == id)) { mx_c = stv[e]; break; }
        }
        float mn_c = sbv[NEXT - 1];
        #pragma unroll 4
        for (int e = 0; e < NEXT; e++) {
            int id = sbi[e];
            if (!__ballot_sync(0xffffffffu, ex == id)) { mn_c = sbv[e]; break; }
        }
        const float mn_s = sh_lo, mx_s = sh_mxs;

        float tv2 = topval[lane];
        int   ti2 = topidx[lane];
        float dg  = sh_diag;

        // logsumexp over extended set (32 neighbors + diagonal)
        float m = tv2;
        #pragma unroll
        for (int o = 16; o > 0; o >>= 1) m = fmaxf(m, __shfl_xor_sync(0xffffffffu, m, o));
        m = fmaxf(m, dg);
        float s = expf(tv2 - m);
        #pragma unroll
        for (int o = 16; o > 0; o >>= 1) s += __shfl_xor_sync(0xffffffffu, s, o);
        s += expf(dg - m);
        float lse = logf(s) + m;

        // positive weights: softmax over neighbors of (norm_sim - norm_cent)*T
        float T  = *temp_p;
        float ns = (tv2 - mn_s) / (mx_s - mn_s);
        float nc = (g_centrality[ti2] - mn_c) / (mx_c - mn_c);
        float a  = (ns - nc) * T;
        float am = a;
        #pragma unroll
        for (int o = 16; o > 0; o >>= 1) am = fmaxf(am, __shfl_xor_sync(0xffffffffu, am, o));
        float pe = expf(a - am);
        float ps = pe;
        #pragma unroll
        for (int o = 16; o > 0; o >>= 1) ps += __shfl_xor_sync(0xffffffffu, ps, o);
        float pw = pe / ps;

        float num   = pw * (tv2 - lse);
        float pwsum = pw;
        #pragma unroll
        for (int o = 16; o > 0; o >>= 1) {
            num   += __shfl_xor_sync(0xffffffffu, num,   o);
            pwsum += __shfl_xor_sync(0xffffffffu, pwsum, o);
        }
        if (lane == 0) {
            float numer = num + (dg - lse);
            float denom = pwsum + 1.0f;
            g_rowloss[i] = -numer / denom;
        }
    }
}

// ---------------------------------------------------------------------------
// Kernel 3: deterministic mean (512 thr, float4 loads, short pairwise chain)
// ---------------------------------------------------------------------------
__global__ __launch_bounds__(TPR) void reduce_kernel(float* __restrict__ out, int B)
{
    const int tid = threadIdx.x, lane = tid & 31, wid = tid >> 5;
    const float4* p = (const float4*)g_rowloss;    // 1024 float4
    float4 a = p[tid];
    float4 b = p[tid + TPR];
    float s = ((a.x + a.y) + (a.z + a.w)) + ((b.x + b.y) + (b.z + b.w));
    __shared__ float ws[TPR / 32];
    #pragma unroll
    for (int o = 16; o > 0; o >>= 1) s += __shfl_down_sync(0xffffffffu, s, o);
    if (lane == 0) ws[wid] = s;
    __syncthreads();
    if (tid < 32) {
        float t = (tid < TPR / 32) ? ws[tid] : 0.f;
        #pragma unroll
        for (int o = 8; o > 0; o >>= 1) t += __shfl_down_sync(0xffffffffu, t, o);
        if (tid == 0) out[0] = t / (float)B;
    }
}

// ---------------------------------------------------------------------------
extern "C" void kernel_launch(void* const* d_in, const int* in_sizes, int n_in,
                              void* d_out, int out_size)
{
    const float* sim  = (const float*)d_in[0];
    const float* mem  = (const float*)d_in[1];
    const float* temp = (const float*)d_in[n_in - 1];

    int nsim = in_sizes[0];
    int B = 1;
    while ((long long)B * B < (long long)nsim) B <<= 1;   // B = 4096
    int M = in_sizes[1] / B;                               // M = 8192

    centrality_kernel<<<B, TPB>>>(mem, B, M);
    cextremes_kernel<<<1, TPB>>>();
    rowloss_kernel<<<B, TPB>>>(sim, temp, B);
    reduce_kernel<<<1, TPR>>>((float*)d_out, B);
}

// round 10
// speedup vs baseline: 1.7798x; 1.4666x over previous
#include <cuda_runtime.h>
#include <float.h>
#include <math.h>

// Problem shape (fixed by dataset): B=4096, M=8192, K=32 neighbors.
#define BMAX  4096
#define TPB   256
#define NW    8
#define KNB   32
#define NBINS 256
#define CAP   512         // candidate capacity (expected ~60)
#define NEXT  34          // centrality extremes kept per end
#define CECAP 256
#define TPR   512         // reduce kernel threads

__device__ float g_centrality[BMAX];
__device__ float g_rowloss[BMAX];
__device__ float g_tv[BMAX][KNB];     // per-row neighbor values
__device__ int   g_ti[BMAX][KNB];     // per-row neighbor indices
__device__ float g_mns[BMAX], g_mxs[BMAX], g_diag[BMAX];
__device__ float g_topv[NEXT]; __device__ int g_topi[NEXT];   // centrality top-34
__device__ float g_botv[NEXT]; __device__ int g_boti[NEXT];   // centrality bot-34

// ---------------------------------------------------------------------------
// Kernel A (grid = 2B, interleaved): even blocks = row selection (sim),
// odd blocks = centrality mean (memory_bank). Co-scheduling mixes the
// bandwidth-bound and latency-bound readers in every wave.
// ---------------------------------------------------------------------------
__global__ __launch_bounds__(TPB) void combined_kernel(
    const float* __restrict__ sim, const float* __restrict__ mem, int B, int M)
{
    __shared__ float    srow[BMAX];
    __shared__ unsigned hist[NBINS];
    __shared__ float    cand_val[CAP];
    __shared__ int      cand_idx[CAP];
    __shared__ float    wmn[NW], wmx[NW];
    __shared__ unsigned sh_cnt;
    __shared__ int      sh_bstar;
    __shared__ float    sh_lo, sh_scale;

    const int tid  = threadIdx.x;
    const int wid  = tid >> 5;
    const int lane = tid & 31;
    const int r    = blockIdx.x >> 1;

    if (blockIdx.x & 1) {
        // ================= centrality path (R5 form, measured) =============
        const float4* p = (const float4*)(mem + (size_t)r * M);
        float4 v0 = p[tid + 0 * TPB];
        float4 v1 = p[tid + 1 * TPB];
        float4 v2 = p[tid + 2 * TPB];
        float4 v3 = p[tid + 3 * TPB];
        float4 v4 = p[tid + 4 * TPB];
        float4 v5 = p[tid + 5 * TPB];
        float4 v6 = p[tid + 6 * TPB];
        float4 v7 = p[tid + 7 * TPB];
        float s = (((v0.x + v0.y) + (v0.z + v0.w)) + ((v1.x + v1.y) + (v1.z + v1.w)))
                + (((v2.x + v2.y) + (v2.z + v2.w)) + ((v3.x + v3.y) + (v3.z + v3.w)))
                + (((v4.x + v4.y) + (v4.z + v4.w)) + ((v5.x + v5.y) + (v5.z + v5.w)))
                + (((v6.x + v6.y) + (v6.z + v6.w)) + ((v7.x + v7.y) + (v7.z + v7.w)));
        #pragma unroll
        for (int o = 16; o > 0; o >>= 1) s += __shfl_down_sync(0xffffffffu, s, o);
        if (lane == 0) wmn[wid] = s;
        __syncthreads();
        if (tid < 32) {
            float t = (tid < NW) ? wmn[tid] : 0.f;
            #pragma unroll
            for (int o = 4; o > 0; o >>= 1) t += __shfl_down_sync(0xffffffffu, t, o);
            if (tid == 0) g_centrality[r] = t / (float)M;
        }
        return;
    }

    // ==================== selection path (R5 body, measured) ===============
    const int i = r;
    float mn = FLT_MAX, mx = -FLT_MAX, tm = -FLT_MAX;
    {
        const float4* rp = (const float4*)(sim + (size_t)i * B);
        const int dq = i >> 2, dl = i & 3;
        #pragma unroll
        for (int k = 0; k < 4; k++) {
            int j = tid + k * TPB;
            float4 v = rp[j];
            ((float4*)srow)[j] = v;                 // raw copy (diag present)
            if (j == dq) {                          // strip diag for stats only
                float dv = (dl == 0) ? v.x : (dl == 1) ? v.y : (dl == 2) ? v.z : v.w;
                g_diag[i] = dv;
                const float rep = (dl == 0) ? v.y : v.x;
                if (dl == 0) v.x = rep; else if (dl == 1) v.y = rep;
                else if (dl == 2) v.z = rep; else v.w = rep;
            }
            float lmx = fmaxf(fmaxf(v.x, v.y), fmaxf(v.z, v.w));
            mn = fminf(mn, fminf(fminf(v.x, v.y), fminf(v.z, v.w)));
            mx = fmaxf(mx, lmx);
            tm = fmaxf(tm, lmx);
        }
        if (tid < NBINS) hist[tid] = 0u;
        if (tid == 0) sh_cnt = 0u;
    }
    #pragma unroll
    for (int o = 16; o > 0; o >>= 1) {
        mn = fminf(mn, __shfl_xor_sync(0xffffffffu, mn, o));
        mx = fmaxf(mx, __shfl_xor_sync(0xffffffffu, mx, o));
    }
    if (lane == 0) { wmn[wid] = mn; wmx[wid] = mx; }
    __syncthreads();
    if (tid == 0) {
        float lo = wmn[0], hi = wmx[0];
        #pragma unroll
        for (int w = 1; w < NW; w++) { lo = fminf(lo, wmn[w]); hi = fmaxf(hi, wmx[w]); }
        sh_lo = lo;
        sh_scale = (float)NBINS / fmaxf(hi - lo, 1e-30f);
        g_mns[i] = lo;                              // mn_s = off-diag row min
    }
    __syncthreads();

    const float lo = sh_lo, scale = sh_scale;

    // histogram the 256 per-thread maxima (one atomic per thread)
    {
        int b = (int)((tm - lo) * scale);
        b = min(max(b, 0), NBINS - 1);
        atomicAdd(&hist[b], 1u);
    }
    __syncthreads();

    // b* = bin of the 33rd-largest thread-max (warp-0 suffix scan)
    if (wid == 0) {
        unsigned running = 0u;
        bool found = false;
        for (int c = 0; c < NBINS / 32 && !found; c++) {
            int bin = NBINS - 1 - c * 32 - lane;
            unsigned p = hist[bin];
            #pragma unroll
            for (int o = 1; o < 32; o <<= 1) {
                unsigned t = __shfl_up_sync(0xffffffffu, p, o);
                if (lane >= o) p += t;
            }
            unsigned cum = running + p;
            unsigned ball = __ballot_sync(0xffffffffu, cum >= 33u);
            running += __shfl_sync(0xffffffffu, p, 31);
            if (ball) {
                if (lane == 0) sh_bstar = NBINS - 1 - c * 32 - (__ffs(ball) - 1);
                found = true;
            }
        }
    }
    __syncthreads();

    // collect candidates with bin >= b*
    {
        const int bstar = sh_bstar;
        #pragma unroll
        for (int k = 0; k < 4; k++) {
            int j = tid + k * TPB;
            float4 v = ((const float4*)srow)[j];
            int base = j << 2;
            #pragma unroll
            for (int e = 0; e < 4; e++) {
                float f = (e == 0) ? v.x : (e == 1) ? v.y : (e == 2) ? v.z : v.w;
                int idx = base + e;
                int b = (int)((f - lo) * scale);
                b = min(max(b, 0), NBINS - 1);
                if (b >= bstar && idx != i) {
                    unsigned pos = atomicAdd(&sh_cnt, 1u);
                    if (pos < CAP) { cand_val[pos] = f; cand_idx[pos] = idx; }
                }
            }
        }
    }
    __syncthreads();

    // exact rank by counting (ties: lower index first, matches top_k);
    // winners go straight to global per-row buffers.
    {
        int n = (int)min(sh_cnt, (unsigned)CAP);
        for (int c = tid; c < n; c += TPB) {
            float v = cand_val[c];
            int   id = cand_idx[c];
            int rk = 0;
            for (int d = 0; d < n; d++) {
                float vd = cand_val[d];
                rk += (vd > v) || (vd == v && cand_idx[d] < id);
            }
            if (rk < KNB) {
                g_tv[i][rk] = v;
                g_ti[i][rk] = id;
            } else if (rk == KNB) {
                g_mxs[i] = v;                       // mx_s = 33rd largest off-diag
            }
        }
    }
}

// ---------------------------------------------------------------------------
// Kernel B: global top-34 / bottom-34 of centrality (one CTA, one-off).
// ---------------------------------------------------------------------------
__global__ __launch_bounds__(TPB) void cextremes_kernel()
{
    __shared__ float    c[BMAX];
    __shared__ unsigned hist[NBINS];
    __shared__ float    tv[CECAP]; __shared__ int ti[CECAP];
    __shared__ float    bv[CECAP]; __shared__ int bi[CECAP];
    __shared__ float    wmn[NW], wmx[NW];
    __shared__ unsigned cntT, cntB;
    __shared__ int      sh_btop, sh_bbot;
    __shared__ float    sh_lo, sh_scale;

    const int tid = threadIdx.x, lane = tid & 31, wid = tid >> 5;
    float mn = FLT_MAX, mx = -FLT_MAX;
    #pragma unroll
    for (int k = 0; k < BMAX / TPB; k++) {
        float v = g_centrality[tid + k * TPB];
        c[tid + k * TPB] = v;
        mn = fminf(mn, v); mx = fmaxf(mx, v);
    }
    if (tid < NBINS) hist[tid] = 0u;
    if (tid == 0) { cntT = 0u; cntB = 0u; }
    #pragma unroll
    for (int o = 16; o > 0; o >>= 1) {
        mn = fminf(mn, __shfl_xor_sync(0xffffffffu, mn, o));
        mx = fmaxf(mx, __shfl_xor_sync(0xffffffffu, mx, o));
    }
    if (lane == 0) { wmn[wid] = mn; wmx[wid] = mx; }
    __syncthreads();
    if (tid == 0) {
        float lo = wmn[0], hi = wmx[0];
        #pragma unroll
        for (int w = 1; w < NW; w++) { lo = fminf(lo, wmn[w]); hi = fmaxf(hi, wmx[w]); }
        sh_lo = lo;
        sh_scale = (float)NBINS / fmaxf(hi - lo, 1e-30f);
    }
    __syncthreads();
    const float lo = sh_lo, scale = sh_scale;
    #pragma unroll
    for (int k = 0; k < BMAX / TPB; k++) {
        int b = (int)((c[tid + k * TPB] - lo) * scale);
        b = min(max(b, 0), NBINS - 1);
        atomicAdd(&hist[b], 1u);
    }
    __syncthreads();
    if (tid == 0) {
        unsigned cum = 0u; int b = NBINS - 1;
        for (; b >= 0; b--) { cum += hist[b]; if (cum >= NEXT) break; }
        sh_btop = b;
        cum = 0u; b = 0;
        for (; b < NBINS; b++) { cum += hist[b]; if (cum >= NEXT) break; }
        sh_bbot = b;
    }
    __syncthreads();
    const int btop = sh_btop, bbot = sh_bbot;
    #pragma unroll
    for (int k = 0; k < BMAX / TPB; k++) {
        int idx = tid + k * TPB;
        float v = c[idx];
        int b = (int)((v - lo) * scale);
        b = min(max(b, 0), NBINS - 1);
        if (b >= btop) { unsigned p = atomicAdd(&cntT, 1u); if (p < CECAP) { tv[p] = v; ti[p] = idx; } }
        if (b <= bbot) { unsigned p = atomicAdd(&cntB, 1u); if (p < CECAP) { bv[p] = v; bi[p] = idx; } }
    }
    __syncthreads();
    {
        int n = (int)min(cntT, (unsigned)CECAP);
        for (int q = tid; q < n; q += TPB) {
            float v = tv[q]; int id = ti[q]; int rk = 0;
            for (int d = 0; d < n; d++) {
                float vd = tv[d];
                rk += (vd > v) || (vd == v && ti[d] < id);
            }
            if (rk < NEXT) { g_topv[rk] = v; g_topi[rk] = id; }
        }
        n = (int)min(cntB, (unsigned)CECAP);
        for (int q = tid; q < n; q += TPB) {
            float v = bv[q]; int id = bi[q]; int rk = 0;
            for (int d = 0; d < n; d++) {
                float vd = bv[d];
                rk += (vd < v) || (vd == v && bi[d] < id);
            }
            if (rk < NEXT) { g_botv[rk] = v; g_boti[rk] = id; }
        }
    }
}

// ---------------------------------------------------------------------------
// Kernel C: per-row epilogue, one warp per row (grid = B/8).
// ---------------------------------------------------------------------------
__global__ __launch_bounds__(TPB) void epilogue_kernel(
    const float* __restrict__ temp_p, int B)
{
    __shared__ float stv[NEXT]; __shared__ int sti[NEXT];
    __shared__ float sbv[NEXT]; __shared__ int sbi[NEXT];

    const int tid = threadIdx.x, wid = tid >> 5, lane = tid & 31;
    if (tid < NEXT) { stv[tid] = g_topv[tid]; sti[tid] = g_topi[tid];
                      sbv[tid] = g_botv[tid]; sbi[tid] = g_boti[tid]; }
    __syncthreads();

    const int r = blockIdx.x * NW + wid;
    float tv2 = g_tv[r][lane];
    int   ti2 = g_ti[r][lane];
    float dg  = g_diag[r];
    const float mn_s = g_mns[r], mx_s = g_mxs[r];

    // centrality extremes over non-excluded (32 neighbors + diagonal r)
    float mx_c = stv[NEXT - 1];
    for (int e = 0; e < NEXT; e++) {
        int id = sti[e];
        bool excl = (__ballot_sync(0xffffffffu, ti2 == id) != 0u) || (id == r);
        if (!excl) { mx_c = stv[e]; break; }
    }
    float mn_c = sbv[NEXT - 1];
    for (int e = 0; e < NEXT; e++) {
        int id = sbi[e];
        bool excl = (__ballot_sync(0xffffffffu, ti2 == id) != 0u) || (id == r);
        if (!excl) { mn_c = sbv[e]; break; }
    }

    // logsumexp over extended set (32 neighbors + diagonal)
    float m = tv2;
    #pragma unroll
    for (int o = 16; o > 0; o >>= 1) m = fmaxf(m, __shfl_xor_sync(0xffffffffu, m, o));
    m = fmaxf(m, dg);
    float s = expf(tv2 - m);
    #pragma unroll
    for (int o = 16; o > 0; o >>= 1) s += __shfl_xor_sync(0xffffffffu, s, o);
    s += expf(dg - m);
    float lse = logf(s) + m;

    // positive weights: softmax over neighbors of (norm_sim - norm_cent)*T
    float T  = *temp_p;
    float ns = (tv2 - mn_s) / (mx_s - mn_s);
    float nc = (g_centrality[ti2] - mn_c) / (mx_c - mn_c);
    float a  = (ns - nc) * T;
    float am = a;
    #pragma unroll
    for (int o = 16; o > 0; o >>= 1) am = fmaxf(am, __shfl_xor_sync(0xffffffffu, am, o));
    float pe = expf(a - am);
    float ps = pe;
    #pragma unroll
    for (int o = 16; o > 0; o >>= 1) ps += __shfl_xor_sync(0xffffffffu, ps, o);
    float pw = pe / ps;

    float num   = pw * (tv2 - lse);
    float pwsum = pw;
    #pragma unroll
    for (int o = 16; o > 0; o >>= 1) {
        num   += __shfl_xor_sync(0xffffffffu, num,   o);
        pwsum += __shfl_xor_sync(0xffffffffu, pwsum, o);
    }
    if (lane == 0) {
        g_rowloss[r] = -(num + (dg - lse)) / (pwsum + 1.0f);
    }
}

// ---------------------------------------------------------------------------
// Kernel D: deterministic mean (512 thr, float4 loads, short pairwise chain)
// ---------------------------------------------------------------------------
__global__ __launch_bounds__(TPR) void reduce_kernel(float* __restrict__ out, int B)
{
    const int tid = threadIdx.x, lane = tid & 31, wid = tid >> 5;
    const float4* p = (const float4*)g_rowloss;    // 1024 float4
    float4 a = p[tid];
    float4 b = p[tid + TPR];
    float s = ((a.x + a.y) + (a.z + a.w)) + ((b.x + b.y) + (b.z + b.w));
    __shared__ float ws[TPR / 32];
    #pragma unroll
    for (int o = 16; o > 0; o >>= 1) s += __shfl_down_sync(0xffffffffu, s, o);
    if (lane == 0) ws[wid] = s;
    __syncthreads();
    if (tid < 32) {
        float t = (tid < TPR / 32) ? ws[tid] : 0.f;
        #pragma unroll
        for (int o = 8; o > 0; o >>= 1) t += __shfl_down_sync(0xffffffffu, t, o);
        if (tid == 0) out[0] = t / (float)B;
    }
}

// ---------------------------------------------------------------------------
extern "C" void kernel_launch(void* const* d_in, const int* in_sizes, int n_in,
                              void* d_out, int out_size)
{
    const float* sim  = (const float*)d_in[0];
    const float* mem  = (const float*)d_in[1];
    const float* temp = (const float*)d_in[n_in - 1];

    int nsim = in_sizes[0];
    int B = 1;
    while ((long long)B * B < (long long)nsim) B <<= 1;   // B = 4096
    int M = in_sizes[1] / B;                               // M = 8192

    combined_kernel<<<2 * B, TPB>>>(sim, mem, B, M);
    cextremes_kernel<<<1, TPB>>>();
    epilogue_kernel<<<B / NW, TPB>>>(temp, B);
    reduce_kernel<<<1, TPR>>>((float*)d_out, B);
}

// round 14
// speedup vs baseline: 1.9148x; 1.0758x over previous
#include <cuda_runtime.h>
#include <float.h>
#include <math.h>

// Problem shape (fixed by dataset): B=4096, M=8192, K=32 neighbors.
#define BMAX  4096
#define TPB   256
#define NW    8
#define KNB   32
#define NBINS 256
#define CAP   512         // candidate capacity (expected ~60)
#define NEXT  34          // centrality extremes kept per end
#define CECAP 256

__device__ float g_centrality[BMAX];
__device__ float g_rowloss[BMAX];
__device__ float g_tv[BMAX][KNB];     // per-row neighbor values
__device__ int   g_ti[BMAX][KNB];     // per-row neighbor indices
__device__ float g_mns[BMAX], g_mxs[BMAX], g_diag[BMAX];
__device__ unsigned g_tick = 0u;      // epilogue last-block ticket

// ---------------------------------------------------------------------------
// Kernel A (grid = 2B, interleaved): even blocks = row selection (sim),
// odd blocks = centrality mean (memory_bank).  UNCHANGED from R10 (measured).
// ---------------------------------------------------------------------------
__global__ __launch_bounds__(TPB) void combined_kernel(
    const float* __restrict__ sim, const float* __restrict__ mem, int B, int M)
{
    __shared__ float    srow[BMAX];
    __shared__ unsigned hist[NBINS];
    __shared__ float    cand_val[CAP];
    __shared__ int      cand_idx[CAP];
    __shared__ float    wmn[NW], wmx[NW];
    __shared__ unsigned sh_cnt;
    __shared__ int      sh_bstar;
    __shared__ float    sh_lo, sh_scale;

    const int tid  = threadIdx.x;
    const int wid  = tid >> 5;
    const int lane = tid & 31;
    const int r    = blockIdx.x >> 1;

    if (blockIdx.x & 1) {
        // ================= centrality path =============
        const float4* p = (const float4*)(mem + (size_t)r * M);
        float4 v0 = p[tid + 0 * TPB];
        float4 v1 = p[tid + 1 * TPB];
        float4 v2 = p[tid + 2 * TPB];
        float4 v3 = p[tid + 3 * TPB];
        float4 v4 = p[tid + 4 * TPB];
        float4 v5 = p[tid + 5 * TPB];
        float4 v6 = p[tid + 6 * TPB];
        float4 v7 = p[tid + 7 * TPB];
        float s = (((v0.x + v0.y) + (v0.z + v0.w)) + ((v1.x + v1.y) + (v1.z + v1.w)))
                + (((v2.x + v2.y) + (v2.z + v2.w)) + ((v3.x + v3.y) + (v3.z + v3.w)))
                + (((v4.x + v4.y) + (v4.z + v4.w)) + ((v5.x + v5.y) + (v5.z + v5.w)))
                + (((v6.x + v6.y) + (v6.z + v6.w)) + ((v7.x + v7.y) + (v7.z + v7.w)));
        #pragma unroll
        for (int o = 16; o > 0; o >>= 1) s += __shfl_down_sync(0xffffffffu, s, o);
        if (lane == 0) wmn[wid] = s;
        __syncthreads();
        if (tid < 32) {
            float t = (tid < NW) ? wmn[tid] : 0.f;
            #pragma unroll
            for (int o = 4; o > 0; o >>= 1) t += __shfl_down_sync(0xffffffffu, t, o);
            if (tid == 0) g_centrality[r] = t / (float)M;
        }
        return;
    }

    // ==================== selection path ===============
    const int i = r;
    float mn = FLT_MAX, mx = -FLT_MAX, tm = -FLT_MAX;
    {
        const float4* rp = (const float4*)(sim + (size_t)i * B);
        const int dq = i >> 2, dl = i & 3;
        #pragma unroll
        for (int k = 0; k < 4; k++) {
            int j = tid + k * TPB;
            float4 v = rp[j];
            ((float4*)srow)[j] = v;                 // raw copy (diag present)
            if (j == dq) {                          // strip diag for stats only
                float dv = (dl == 0) ? v.x : (dl == 1) ? v.y : (dl == 2) ? v.z : v.w;
                g_diag[i] = dv;
                const float rep = (dl == 0) ? v.y : v.x;
                if (dl == 0) v.x = rep; else if (dl == 1) v.y = rep;
                else if (dl == 2) v.z = rep; else v.w = rep;
            }
            float lmx = fmaxf(fmaxf(v.x, v.y), fmaxf(v.z, v.w));
            mn = fminf(mn, fminf(fminf(v.x, v.y), fminf(v.z, v.w)));
            mx = fmaxf(mx, lmx);
            tm = fmaxf(tm, lmx);
        }
        if (tid < NBINS) hist[tid] = 0u;
        if (tid == 0) sh_cnt = 0u;
    }
    #pragma unroll
    for (int o = 16; o > 0; o >>= 1) {
        mn = fminf(mn, __shfl_xor_sync(0xffffffffu, mn, o));
        mx = fmaxf(mx, __shfl_xor_sync(0xffffffffu, mx, o));
    }
    if (lane == 0) { wmn[wid] = mn; wmx[wid] = mx; }
    __syncthreads();
    if (tid == 0) {
        float lo = wmn[0], hi = wmx[0];
        #pragma unroll
        for (int w = 1; w < NW; w++) { lo = fminf(lo, wmn[w]); hi = fmaxf(hi, wmx[w]); }
        sh_lo = lo;
        sh_scale = (float)NBINS / fmaxf(hi - lo, 1e-30f);
        g_mns[i] = lo;                              // mn_s = off-diag row min
    }
    __syncthreads();

    const float lo = sh_lo, scale = sh_scale;

    // histogram the 256 per-thread maxima (one atomic per thread)
    {
        int b = (int)((tm - lo) * scale);
        b = min(max(b, 0), NBINS - 1);
        atomicAdd(&hist[b], 1u);
    }
    __syncthreads();

    // b* = bin of the 33rd-largest thread-max (warp-0 suffix scan)
    if (wid == 0) {
        unsigned running = 0u;
        bool found = false;
        for (int c = 0; c < NBINS / 32 && !found; c++) {
            int bin = NBINS - 1 - c * 32 - lane;
            unsigned p = hist[bin];
            #pragma unroll
            for (int o = 1; o < 32; o <<= 1) {
                unsigned t = __shfl_up_sync(0xffffffffu, p, o);
                if (lane >= o) p += t;
            }
            unsigned cum = running + p;
            unsigned ball = __ballot_sync(0xffffffffu, cum >= 33u);
            running += __shfl_sync(0xffffffffu, p, 31);
            if (ball) {
                if (lane == 0) sh_bstar = NBINS - 1 - c * 32 - (__ffs(ball) - 1);
                found = true;
            }
        }
    }
    __syncthreads();

    // collect candidates with bin >= b*
    {
        const int bstar = sh_bstar;
        #pragma unroll
        for (int k = 0; k < 4; k++) {
            int j = tid + k * TPB;
            float4 v = ((const float4*)srow)[j];
            int base = j << 2;
            #pragma unroll
            for (int e = 0; e < 4; e++) {
                float f = (e == 0) ? v.x : (e == 1) ? v.y : (e == 2) ? v.z : v.w;
                int idx = base + e;
                int b = (int)((f - lo) * scale);
                b = min(max(b, 0), NBINS - 1);
                if (b >= bstar && idx != i) {
                    unsigned pos = atomicAdd(&sh_cnt, 1u);
                    if (pos < CAP) { cand_val[pos] = f; cand_idx[pos] = idx; }
                }
            }
        }
    }
    __syncthreads();

    // exact rank by counting (ties: lower index first, matches top_k)
    {
        int n = (int)min(sh_cnt, (unsigned)CAP);
        for (int c = tid; c < n; c += TPB) {
            float v = cand_val[c];
            int   id = cand_idx[c];
            int rk = 0;
            for (int d = 0; d < n; d++) {
                float vd = cand_val[d];
                rk += (vd > v) || (vd == v && cand_idx[d] < id);
            }
            if (rk < KNB) {
                g_tv[i][rk] = v;
                g_ti[i][rk] = id;
            } else if (rk == KNB) {
                g_mxs[i] = v;                       // mx_s = 33rd largest off-diag
            }
        }
    }
}

// ---------------------------------------------------------------------------
// Kernel B (grid = B/NW = 512): fused epilogue.
//   Phase 1: every CTA redundantly computes centrality top/bot-34 from an
//            smem-staged copy (deterministic, no inter-CTA dependency).
//   Phase 2: 8 warps x 1 row each -> g_rowloss.
//   Phase 3: last-CTA ticket -> deterministic mean into d_out.
// ---------------------------------------------------------------------------
__global__ __launch_bounds__(TPB) void epilogue_kernel(
    const float* __restrict__ temp_p, float* __restrict__ out, int B)
{
    __shared__ float    c[BMAX];
    __shared__ unsigned hist[NBINS];
    __shared__ float    tv[CECAP]; __shared__ int ti[CECAP];
    __shared__ float    bv[CECAP]; __shared__ int bi[CECAP];
    __shared__ float    stv[NEXT]; __shared__ int sti[NEXT];
    __shared__ float    sbv[NEXT]; __shared__ int sbi[NEXT];
    __shared__ float    wmn[NW], wmx[NW];
    __shared__ unsigned cntT, cntB;
    __shared__ int      sh_btop, sh_bbot;
    __shared__ float    sh_lo, sh_scale;

    const int tid = threadIdx.x, lane = tid & 31, wid = tid >> 5;

    // ---- Phase 1: centrality extremes (cextremes body, per-CTA) ----
    float mn = FLT_MAX, mx = -FLT_MAX;
    #pragma unroll
    for (int k = 0; k < BMAX / TPB; k++) {
        float v = g_centrality[tid + k * TPB];
        c[tid + k * TPB] = v;
        mn = fminf(mn, v); mx = fmaxf(mx, v);
    }
    if (tid < NBINS) hist[tid] = 0u;
    if (tid == 0) { cntT = 0u; cntB = 0u; }
    #pragma unroll
    for (int o = 16; o > 0; o >>= 1) {
        mn = fminf(mn, __shfl_xor_sync(0xffffffffu, mn, o));
        mx = fmaxf(mx, __shfl_xor_sync(0xffffffffu, mx, o));
    }
    if (lane == 0) { wmn[wid] = mn; wmx[wid] = mx; }
    __syncthreads();
    if (tid == 0) {
        float lo = wmn[0], hi = wmx[0];
        #pragma unroll
        for (int w = 1; w < NW; w++) { lo = fminf(lo, wmn[w]); hi = fmaxf(hi, wmx[w]); }
        sh_lo = lo;
        sh_scale = (float)NBINS / fmaxf(hi - lo, 1e-30f);
    }
    __syncthreads();
    {
        const float lo = sh_lo, scale = sh_scale;
        #pragma unroll
        for (int k = 0; k < BMAX / TPB; k++) {
            int b = (int)((c[tid + k * TPB] - lo) * scale);
            b = min(max(b, 0), NBINS - 1);
            atomicAdd(&hist[b], 1u);
        }
        __syncthreads();
        if (tid == 0) {
            unsigned cum = 0u; int b = NBINS - 1;
            for (; b >= 0; b--) { cum += hist[b]; if (cum >= NEXT) break; }
            sh_btop = b;
            cum = 0u; b = 0;
            for (; b < NBINS; b++) { cum += hist[b]; if (cum >= NEXT) break; }
            sh_bbot = b;
        }
        __syncthreads();
        const int btop = sh_btop, bbot = sh_bbot;
        #pragma unroll
        for (int k = 0; k < BMAX / TPB; k++) {
            int idx = tid + k * TPB;
            float v = c[idx];
            int b = (int)((v - lo) * scale);
            b = min(max(b, 0), NBINS - 1);
            if (b >= btop) { unsigned p = atomicAdd(&cntT, 1u); if (p < CECAP) { tv[p] = v; ti[p] = idx; } }
            if (b <= bbot) { unsigned p = atomicAdd(&cntB, 1u); if (p < CECAP) { bv[p] = v; bi[p] = idx; } }
        }
        __syncthreads();
        int n = (int)min(cntT, (unsigned)CECAP);
        for (int q = tid; q < n; q += TPB) {
            float v = tv[q]; int id = ti[q]; int rk = 0;
            for (int d = 0; d < n; d++) {
                float vd = tv[d];
                rk += (vd > v) || (vd == v && ti[d] < id);
            }
            if (rk < NEXT) { stv[rk] = v; sti[rk] = id; }
        }
        n = (int)min(cntB, (unsigned)CECAP);
        for (int q = tid; q < n; q += TPB) {
            float v = bv[q]; int id = bi[q]; int rk = 0;
            for (int d = 0; d < n; d++) {
                float vd = bv[d];
                rk += (vd < v) || (vd == v && bi[d] < id);
            }
            if (rk < NEXT) { sbv[rk] = v; sbi[rk] = id; }
        }
    }
    __syncthreads();

    // ---- Phase 2: one warp per row ----
    {
        const int r = blockIdx.x * NW + wid;
        float tv2 = g_tv[r][lane];
        int   ti2 = g_ti[r][lane];
        float dg  = g_diag[r];
        const float mn_s = g_mns[r], mx_s = g_mxs[r];

        // centrality extremes over non-excluded (32 neighbors + diagonal r)
        float mx_c = stv[NEXT - 1];
        for (int e = 0; e < NEXT; e++) {
            int id = sti[e];
            bool excl = (__ballot_sync(0xffffffffu, ti2 == id) != 0u) || (id == r);
            if (!excl) { mx_c = stv[e]; break; }
        }
        float mn_c = sbv[NEXT - 1];
        for (int e = 0; e < NEXT; e++) {
            int id = sbi[e];
            bool excl = (__ballot_sync(0xffffffffu, ti2 == id) != 0u) || (id == r);
            if (!excl) { mn_c = sbv[e]; break; }
        }

        // logsumexp over extended set (32 neighbors + diagonal)
        float m = tv2;
        #pragma unroll
        for (int o = 16; o > 0; o >>= 1) m = fmaxf(m, __shfl_xor_sync(0xffffffffu, m, o));
        m = fmaxf(m, dg);
        float s = expf(tv2 - m);
        #pragma unroll
        for (int o = 16; o > 0; o >>= 1) s += __shfl_xor_sync(0xffffffffu, s, o);
        s += expf(dg - m);
        float lse = logf(s) + m;

        // positive weights: softmax over neighbors of (norm_sim - norm_cent)*T
        float T  = *temp_p;
        float ns = (tv2 - mn_s) / (mx_s - mn_s);
        float nc = (c[ti2] - mn_c) / (mx_c - mn_c);   // smem-staged centrality
        float a  = (ns - nc) * T;
        float am = a;
        #pragma unroll
        for (int o = 16; o > 0; o >>= 1) am = fmaxf(am, __shfl_xor_sync(0xffffffffu, am, o));
        float pe = expf(a - am);
        float ps = pe;
        #pragma unroll
        for (int o = 16; o > 0; o >>= 1) ps += __shfl_xor_sync(0xffffffffu, ps, o);
        float pw = pe / ps;

        float num   = pw * (tv2 - lse);
        float pwsum = pw;
        #pragma unroll
        for (int o = 16; o > 0; o >>= 1) {
            num   += __shfl_xor_sync(0xffffffffu, num,   o);
            pwsum += __shfl_xor_sync(0xffffffffu, pwsum, o);
        }
        if (lane == 0) {
            g_rowloss[r] = -(num + (dg - lse)) / (pwsum + 1.0f);
        }
    }

    // ---- Phase 3: last-CTA ticket -> deterministic mean ----
    __shared__ bool is_last;
    __syncthreads();
    if (tid == 0) {
        __threadfence();                            // publish this CTA's rows
        unsigned o = atomicAdd(&g_tick, 1u);
        is_last = (o == (unsigned)gridDim.x - 1u);
        if (is_last) g_tick = 0u;                   // reset for graph replay
    }
    __syncthreads();
    if (!is_last) return;
    __threadfence();                                // see all rows

    float s = 0.f;
    {
        const float4* p = (const float4*)g_rowloss;    // 1024 float4
        float4 a0 = p[tid];
        float4 a1 = p[tid + TPB];
        float4 a2 = p[tid + 2 * TPB];
        float4 a3 = p[tid + 3 * TPB];
        s = (((a0.x + a0.y) + (a0.z + a0.w)) + ((a1.x + a1.y) + (a1.z + a1.w)))
          + (((a2.x + a2.y) + (a2.z + a2.w)) + ((a3.x + a3.y) + (a3.z + a3.w)));
    }
    __shared__ float wsd[NW];
    #pragma unroll
    for (int o = 16; o > 0; o >>= 1) s += __shfl_down_sync(0xffffffffu, s, o);
    if (lane == 0) wsd[wid] = s;
    __syncthreads();
    if (tid < 32) {
        float t = (tid < NW) ? wsd[tid] : 0.f;
        #pragma unroll
        for (int o = 4; o > 0; o >>= 1) t += __shfl_down_sync(0xffffffffu, t, o);
        if (tid == 0) out[0] = t / (float)B;
    }
}

// ---------------------------------------------------------------------------
extern "C" void kernel_launch(void* const* d_in, const int* in_sizes, int n_in,
                              void* d_out, int out_size)
{
    const float* sim  = (const float*)d_in[0];
    const float* mem  = (const float*)d_in[1];
    const float* temp = (const float*)d_in[n_in - 1];

    int nsim = in_sizes[0];
    int B = 1;
    while ((long long)B * B < (long long)nsim) B <<= 1;   // B = 4096
    int M = in_sizes[1] / B;                               // M = 8192

    combined_kernel<<<2 * B, TPB>>>(sim, mem, B, M);
    epilogue_kernel<<<B / NW, TPB>>>(temp, (float*)d_out, B);
}

// round 15
// speedup vs baseline: 1.9704x; 1.0290x over previous
#include <cuda_runtime.h>
#include <float.h>
#include <math.h>

// Problem shape (fixed by dataset): B=4096, M=8192, K=32 neighbors.
#define BMAX  4096
#define TPB   256
#define NW    8
#define KNB   32
#define NBINS 256
#define CAP   512         // candidate capacity (expected ~60)
#define NEXT  34          // centrality extremes kept per end
#define CECAP 256

__device__ float g_centrality[BMAX];
__device__ float g_rowloss[BMAX];
__device__ float g_tv[BMAX][KNB];     // per-row neighbor values
__device__ int   g_ti[BMAX][KNB];     // per-row neighbor indices
__device__ float g_mns[BMAX], g_mxs[BMAX], g_diag[BMAX];
__device__ unsigned g_tick = 0u;      // epilogue last-block ticket

// ---------------------------------------------------------------------------
// Kernel A (grid = 2B, interleaved): even blocks = row selection (sim),
// odd blocks = centrality mean (memory_bank).  UNCHANGED (measured winner).
// ---------------------------------------------------------------------------
__global__ __launch_bounds__(TPB) void combined_kernel(
    const float* __restrict__ sim, const float* __restrict__ mem, int B, int M)
{
    __shared__ float    srow[BMAX];
    __shared__ unsigned hist[NBINS];
    __shared__ float    cand_val[CAP];
    __shared__ int      cand_idx[CAP];
    __shared__ float    wmn[NW], wmx[NW];
    __shared__ unsigned sh_cnt;
    __shared__ int      sh_bstar;
    __shared__ float    sh_lo, sh_scale;

    const int tid  = threadIdx.x;
    const int wid  = tid >> 5;
    const int lane = tid & 31;
    const int r    = blockIdx.x >> 1;

    if (blockIdx.x & 1) {
        // ================= centrality path =============
        const float4* p = (const float4*)(mem + (size_t)r * M);
        float4 v0 = p[tid + 0 * TPB];
        float4 v1 = p[tid + 1 * TPB];
        float4 v2 = p[tid + 2 * TPB];
        float4 v3 = p[tid + 3 * TPB];
        float4 v4 = p[tid + 4 * TPB];
        float4 v5 = p[tid + 5 * TPB];
        float4 v6 = p[tid + 6 * TPB];
        float4 v7 = p[tid + 7 * TPB];
        float s = (((v0.x + v0.y) + (v0.z + v0.w)) + ((v1.x + v1.y) + (v1.z + v1.w)))
                + (((v2.x + v2.y) + (v2.z + v2.w)) + ((v3.x + v3.y) + (v3.z + v3.w)))
                + (((v4.x + v4.y) + (v4.z + v4.w)) + ((v5.x + v5.y) + (v5.z + v5.w)))
                + (((v6.x + v6.y) + (v6.z + v6.w)) + ((v7.x + v7.y) + (v7.z + v7.w)));
        #pragma unroll
        for (int o = 16; o > 0; o >>= 1) s += __shfl_down_sync(0xffffffffu, s, o);
        if (lane == 0) wmn[wid] = s;
        __syncthreads();
        if (tid < 32) {
            float t = (tid < NW) ? wmn[tid] : 0.f;
            #pragma unroll
            for (int o = 4; o > 0; o >>= 1) t += __shfl_down_sync(0xffffffffu, t, o);
            if (tid == 0) g_centrality[r] = t / (float)M;
        }
        return;
    }

    // ==================== selection path ===============
    const int i = r;
    float mn = FLT_MAX, mx = -FLT_MAX, tm = -FLT_MAX;
    {
        const float4* rp = (const float4*)(sim + (size_t)i * B);
        const int dq = i >> 2, dl = i & 3;
        #pragma unroll
        for (int k = 0; k < 4; k++) {
            int j = tid + k * TPB;
            float4 v = rp[j];
            ((float4*)srow)[j] = v;                 // raw copy (diag present)
            if (j == dq) {                          // strip diag for stats only
                float dv = (dl == 0) ? v.x : (dl == 1) ? v.y : (dl == 2) ? v.z : v.w;
                g_diag[i] = dv;
                const float rep = (dl == 0) ? v.y : v.x;
                if (dl == 0) v.x = rep; else if (dl == 1) v.y = rep;
                else if (dl == 2) v.z = rep; else v.w = rep;
            }
            float lmx = fmaxf(fmaxf(v.x, v.y), fmaxf(v.z, v.w));
            mn = fminf(mn, fminf(fminf(v.x, v.y), fminf(v.z, v.w)));
            mx = fmaxf(mx, lmx);
            tm = fmaxf(tm, lmx);
        }
        if (tid < NBINS) hist[tid] = 0u;
        if (tid == 0) sh_cnt = 0u;
    }
    #pragma unroll
    for (int o = 16; o > 0; o >>= 1) {
        mn = fminf(mn, __shfl_xor_sync(0xffffffffu, mn, o));
        mx = fmaxf(mx, __shfl_xor_sync(0xffffffffu, mx, o));
    }
    if (lane == 0) { wmn[wid] = mn; wmx[wid] = mx; }
    __syncthreads();
    if (tid == 0) {
        float lo = wmn[0], hi = wmx[0];
        #pragma unroll
        for (int w = 1; w < NW; w++) { lo = fminf(lo, wmn[w]); hi = fmaxf(hi, wmx[w]); }
        sh_lo = lo;
        sh_scale = (float)NBINS / fmaxf(hi - lo, 1e-30f);
        g_mns[i] = lo;                              // mn_s = off-diag row min
    }
    __syncthreads();

    const float lo = sh_lo, scale = sh_scale;

    // histogram the 256 per-thread maxima (one atomic per thread)
    {
        int b = (int)((tm - lo) * scale);
        b = min(max(b, 0), NBINS - 1);
        atomicAdd(&hist[b], 1u);
    }
    __syncthreads();

    // b* = bin of the 33rd-largest thread-max (warp-0 suffix scan)
    if (wid == 0) {
        unsigned running = 0u;
        bool found = false;
        for (int c = 0; c < NBINS / 32 && !found; c++) {
            int bin = NBINS - 1 - c * 32 - lane;
            unsigned p = hist[bin];
            #pragma unroll
            for (int o = 1; o < 32; o <<= 1) {
                unsigned t = __shfl_up_sync(0xffffffffu, p, o);
                if (lane >= o) p += t;
            }
            unsigned cum = running + p;
            unsigned ball = __ballot_sync(0xffffffffu, cum >= 33u);
            running += __shfl_sync(0xffffffffu, p, 31);
            if (ball) {
                if (lane == 0) sh_bstar = NBINS - 1 - c * 32 - (__ffs(ball) - 1);
                found = true;
            }
        }
    }
    __syncthreads();

    // collect candidates with bin >= b*
    {
        const int bstar = sh_bstar;
        #pragma unroll
        for (int k = 0; k < 4; k++) {
            int j = tid + k * TPB;
            float4 v = ((const float4*)srow)[j];
            int base = j << 2;
            #pragma unroll
            for (int e = 0; e < 4; e++) {
                float f = (e == 0) ? v.x : (e == 1) ? v.y : (e == 2) ? v.z : v.w;
                int idx = base + e;
                int b = (int)((f - lo) * scale);
                b = min(max(b, 0), NBINS - 1);
                if (b >= bstar && idx != i) {
                    unsigned pos = atomicAdd(&sh_cnt, 1u);
                    if (pos < CAP) { cand_val[pos] = f; cand_idx[pos] = idx; }
                }
            }
        }
    }
    __syncthreads();

    // exact rank by counting (ties: lower index first, matches top_k)
    {
        int n = (int)min(sh_cnt, (unsigned)CAP);
        for (int c = tid; c < n; c += TPB) {
            float v = cand_val[c];
            int   id = cand_idx[c];
            int rk = 0;
            for (int d = 0; d < n; d++) {
                float vd = cand_val[d];
                rk += (vd > v) || (vd == v && cand_idx[d] < id);
            }
            if (rk < KNB) {
                g_tv[i][rk] = v;
                g_ti[i][rk] = id;
            } else if (rk == KNB) {
                g_mxs[i] = v;                       // mx_s = 33rd largest off-diag
            }
        }
    }
}

// ---------------------------------------------------------------------------
// Kernel B (grid = B/NW = 512): fused epilogue.
//   Phase 1: every CTA redundantly computes centrality top/bot-34 from an
//            smem-staged copy.  Boundary bins found by PARALLEL warp scans
//            (warp 0 = top, warp 1 = bottom) — no serial 256-iter LDS chain.
//   Phase 2: 8 warps x 1 row each -> g_rowloss.
//   Phase 3: last-CTA ticket -> deterministic mean into d_out.
// ---------------------------------------------------------------------------
__global__ __launch_bounds__(TPB) void epilogue_kernel(
    const float* __restrict__ temp_p, float* __restrict__ out, int B)
{
    __shared__ float    c[BMAX];
    __shared__ unsigned hist[NBINS];
    __shared__ float    tv[CECAP]; __shared__ int ti[CECAP];
    __shared__ float    bv[CECAP]; __shared__ int bi[CECAP];
    __shared__ float    stv[NEXT]; __shared__ int sti[NEXT];
    __shared__ float    sbv[NEXT]; __shared__ int sbi[NEXT];
    __shared__ float    wmn[NW], wmx[NW];
    __shared__ unsigned cntT, cntB;
    __shared__ int      sh_btop, sh_bbot;
    __shared__ float    sh_lo, sh_scale;

    const int tid = threadIdx.x, lane = tid & 31, wid = tid >> 5;

    // ---- Phase 1: centrality extremes ----
    float mn = FLT_MAX, mx = -FLT_MAX;
    #pragma unroll
    for (int k = 0; k < BMAX / TPB; k++) {
        float v = g_centrality[tid + k * TPB];
        c[tid + k * TPB] = v;
        mn = fminf(mn, v); mx = fmaxf(mx, v);
    }
    if (tid < NBINS) hist[tid] = 0u;
    if (tid == 0) { cntT = 0u; cntB = 0u; }
    #pragma unroll
    for (int o = 16; o > 0; o >>= 1) {
        mn = fminf(mn, __shfl_xor_sync(0xffffffffu, mn, o));
        mx = fmaxf(mx, __shfl_xor_sync(0xffffffffu, mx, o));
    }
    if (lane == 0) { wmn[wid] = mn; wmx[wid] = mx; }
    __syncthreads();
    if (tid == 0) {
        float lo = wmn[0], hi = wmx[0];
        #pragma unroll
        for (int w = 1; w < NW; w++) { lo = fminf(lo, wmn[w]); hi = fmaxf(hi, wmx[w]); }
        sh_lo = lo;
        sh_scale = (float)NBINS / fmaxf(hi - lo, 1e-30f);
    }
    __syncthreads();
    {
        const float lo = sh_lo, scale = sh_scale;
        #pragma unroll
        for (int k = 0; k < BMAX / TPB; k++) {
            int b = (int)((c[tid + k * TPB] - lo) * scale);
            b = min(max(b, 0), NBINS - 1);
            atomicAdd(&hist[b], 1u);
        }
        __syncthreads();

        // parallel boundary scans: warp 0 -> btop (suffix from top),
        //                          warp 1 -> bbot (prefix from bottom)
        if (wid == 0) {
            unsigned running = 0u;
            bool found = false;
            for (int cc = 0; cc < NBINS / 32 && !found; cc++) {
                int bin = NBINS - 1 - cc * 32 - lane;
                unsigned p = hist[bin];
                #pragma unroll
                for (int o = 1; o < 32; o <<= 1) {
                    unsigned t = __shfl_up_sync(0xffffffffu, p, o);
                    if (lane >= o) p += t;
                }
                unsigned cum = running + p;
                unsigned ball = __ballot_sync(0xffffffffu, cum >= NEXT);
                running += __shfl_sync(0xffffffffu, p, 31);
                if (ball) {
                    if (lane == 0) sh_btop = NBINS - 1 - cc * 32 - (__ffs(ball) - 1);
                    found = true;
                }
            }
            if (!found && lane == 0) sh_btop = 0;
        } else if (wid == 1) {
            unsigned running = 0u;
            bool found = false;
            for (int cc = 0; cc < NBINS / 32 && !found; cc++) {
                int bin = cc * 32 + lane;
                unsigned p = hist[bin];
                #pragma unroll
                for (int o = 1; o < 32; o <<= 1) {
                    unsigned t = __shfl_up_sync(0xffffffffu, p, o);
                    if (lane >= o) p += t;
                }
                unsigned cum = running + p;
                unsigned ball = __ballot_sync(0xffffffffu, cum >= NEXT);
                running += __shfl_sync(0xffffffffu, p, 31);
                if (ball) {
                    if (lane == 0) sh_bbot = cc * 32 + (__ffs(ball) - 1);
                    found = true;
                }
            }
            if (!found && lane == 0) sh_bbot = NBINS - 1;
        }
        __syncthreads();
        const int btop = sh_btop, bbot = sh_bbot;
        #pragma unroll
        for (int k = 0; k < BMAX / TPB; k++) {
            int idx = tid + k * TPB;
            float v = c[idx];
            int b = (int)((v - lo) * scale);
            b = min(max(b, 0), NBINS - 1);
            if (b >= btop) { unsigned p = atomicAdd(&cntT, 1u); if (p < CECAP) { tv[p] = v; ti[p] = idx; } }
            if (b <= bbot) { unsigned p = atomicAdd(&cntB, 1u); if (p < CECAP) { bv[p] = v; bi[p] = idx; } }
        }
        __syncthreads();
        int n = (int)min(cntT, (unsigned)CECAP);
        for (int q = tid; q < n; q += TPB) {
            float v = tv[q]; int id = ti[q]; int rk = 0;
            for (int d = 0; d < n; d++) {
                float vd = tv[d];
                rk += (vd > v) || (vd == v && ti[d] < id);
            }
            if (rk < NEXT) { stv[rk] = v; sti[rk] = id; }
        }
        n = (int)min(cntB, (unsigned)CECAP);
        for (int q = tid; q < n; q += TPB) {
            float v = bv[q]; int id = bi[q]; int rk = 0;
            for (int d = 0; d < n; d++) {
                float vd = bv[d];
                rk += (vd < v) || (vd == v && bi[d] < id);
            }
            if (rk < NEXT) { sbv[rk] = v; sbi[rk] = id; }
        }
    }
    __syncthreads();

    // ---- Phase 2: one warp per row ----
    {
        const int r = blockIdx.x * NW + wid;
        float tv2 = g_tv[r][lane];
        int   ti2 = g_ti[r][lane];
        float dg  = g_diag[r];
        const float mn_s = g_mns[r], mx_s = g_mxs[r];

        // centrality extremes over non-excluded (32 neighbors + diagonal r)
        float mx_c = stv[NEXT - 1];
        for (int e = 0; e < NEXT; e++) {
            int id = sti[e];
            bool excl = (__ballot_sync(0xffffffffu, ti2 == id) != 0u) || (id == r);
            if (!excl) { mx_c = stv[e]; break; }
        }
        float mn_c = sbv[NEXT - 1];
        for (int e = 0; e < NEXT; e++) {
            int id = sbi[e];
            bool excl = (__ballot_sync(0xffffffffu, ti2 == id) != 0u) || (id == r);
            if (!excl) { mn_c = sbv[e]; break; }
        }

        // logsumexp over extended set (32 neighbors + diagonal)
        float m = tv2;
        #pragma unroll
        for (int o = 16; o > 0; o >>= 1) m = fmaxf(m, __shfl_xor_sync(0xffffffffu, m, o));
        m = fmaxf(m, dg);
        float s = expf(tv2 - m);
        #pragma unroll
        for (int o = 16; o > 0; o >>= 1) s += __shfl_xor_sync(0xffffffffu, s, o);
        s += expf(dg - m);
        float lse = logf(s) + m;

        // positive weights: softmax over neighbors of (norm_sim - norm_cent)*T
        float T  = *temp_p;
        float ns = (tv2 - mn_s) / (mx_s - mn_s);
        float nc = (c[ti2] - mn_c) / (mx_c - mn_c);   // smem-staged centrality
        float a  = (ns - nc) * T;
        float am = a;
        #pragma unroll
        for (int o = 16; o > 0; o >>= 1) am = fmaxf(am, __shfl_xor_sync(0xffffffffu, am, o));
        float pe = expf(a - am);
        float ps = pe;
        #pragma unroll
        for (int o = 16; o > 0; o >>= 1) ps += __shfl_xor_sync(0xffffffffu, ps, o);
        float pw = pe / ps;

        float num   = pw * (tv2 - lse);
        float pwsum = pw;
        #pragma unroll
        for (int o = 16; o > 0; o >>= 1) {
            num   += __shfl_xor_sync(0xffffffffu, num,   o);
            pwsum += __shfl_xor_sync(0xffffffffu, pwsum, o);
        }
        if (lane == 0) {
            g_rowloss[r] = -(num + (dg - lse)) / (pwsum + 1.0f);
        }
    }

    // ---- Phase 3: last-CTA ticket -> deterministic mean ----
    __shared__ bool is_last;
    __syncthreads();
    if (tid == 0) {
        __threadfence();                            // publish this CTA's rows
        unsigned o = atomicAdd(&g_tick, 1u);
        is_last = (o == (unsigned)gridDim.x - 1u);
        if (is_last) g_tick = 0u;                   // reset for graph replay
    }
    __syncthreads();
    if (!is_last) return;
    __threadfence();                                // see all rows

    float s = 0.f;
    {
        const float4* p = (const float4*)g_rowloss;    // 1024 float4
        float4 a0 = p[tid];
        float4 a1 = p[tid + TPB];
        float4 a2 = p[tid + 2 * TPB];
        float4 a3 = p[tid + 3 * TPB];
        s = (((a0.x + a0.y) + (a0.z + a0.w)) + ((a1.x + a1.y) + (a1.z + a1.w)))
          + (((a2.x + a2.y) + (a2.z + a2.w)) + ((a3.x + a3.y) + (a3.z + a3.w)));
    }
    __shared__ float wsd[NW];
    #pragma unroll
    for (int o = 16; o > 0; o >>= 1) s += __shfl_down_sync(0xffffffffu, s, o);
    if (lane == 0) wsd[wid] = s;
    __syncthreads();
    if (tid < 32) {
        float t = (tid < NW) ? wsd[tid] : 0.f;
        #pragma unroll
        for (int o = 4; o > 0; o >>= 1) t += __shfl_down_sync(0xffffffffu, t, o);
        if (tid == 0) out[0] = t / (float)B;
    }
}

// ---------------------------------------------------------------------------
extern "C" void kernel_launch(void* const* d_in, const int* in_sizes, int n_in,
                              void* d_out, int out_size)
{
    const float* sim  = (const float*)d_in[0];
    const float* mem  = (const float*)d_in[1];
    const float* temp = (const float*)d_in[n_in - 1];

    int nsim = in_sizes[0];
    int B = 1;
    while ((long long)B * B < (long long)nsim) B <<= 1;   // B = 4096
    int M = in_sizes[1] / B;                               // M = 8192

    combined_kernel<<<2 * B, TPB>>>(sim, mem, B, M);
    epilogue_kernel<<<B / NW, TPB>>>(temp, (float*)d_out, B);
}

// round 16
// speedup vs baseline: 1.9760x; 1.0029x over previous
#include <cuda_runtime.h>
#include <float.h>
#include <math.h>

// Problem shape (fixed by dataset): B=4096, M=8192, K=32 neighbors.
#define BMAX  4096
#define TPB   256
#define NW    8
#define KNB   32
#define NBINS 256
#define CAP   512         // candidate capacity (expected ~60)
#define NEXT  34          // centrality extremes kept per end
#define CECAP 512

__device__ float g_centrality[BMAX];
__device__ float g_rowloss[BMAX];
__device__ float g_tv[BMAX][KNB];     // per-row neighbor values
__device__ int   g_ti[BMAX][KNB];     // per-row neighbor indices
__device__ float g_mns[BMAX], g_mxs[BMAX], g_diag[BMAX];
__device__ unsigned g_tick = 0u;      // epilogue last-block ticket

// ---------------------------------------------------------------------------
// Kernel A (grid = 2B, interleaved): even blocks = row selection (sim),
// odd blocks = centrality mean (memory_bank).  UNCHANGED (measured winner).
// ---------------------------------------------------------------------------
__global__ __launch_bounds__(TPB) void combined_kernel(
    const float* __restrict__ sim, const float* __restrict__ mem, int B, int M)
{
    __shared__ float    srow[BMAX];
    __shared__ unsigned hist[NBINS];
    __shared__ float    cand_val[CAP];
    __shared__ int      cand_idx[CAP];
    __shared__ float    wmn[NW], wmx[NW];
    __shared__ unsigned sh_cnt;
    __shared__ int      sh_bstar;
    __shared__ float    sh_lo, sh_scale;

    const int tid  = threadIdx.x;
    const int wid  = tid >> 5;
    const int lane = tid & 31;
    const int r    = blockIdx.x >> 1;

    if (blockIdx.x & 1) {
        // ================= centrality path =============
        const float4* p = (const float4*)(mem + (size_t)r * M);
        float4 v0 = p[tid + 0 * TPB];
        float4 v1 = p[tid + 1 * TPB];
        float4 v2 = p[tid + 2 * TPB];
        float4 v3 = p[tid + 3 * TPB];
        float4 v4 = p[tid + 4 * TPB];
        float4 v5 = p[tid + 5 * TPB];
        float4 v6 = p[tid + 6 * TPB];
        float4 v7 = p[tid + 7 * TPB];
        float s = (((v0.x + v0.y) + (v0.z + v0.w)) + ((v1.x + v1.y) + (v1.z + v1.w)))
                + (((v2.x + v2.y) + (v2.z + v2.w)) + ((v3.x + v3.y) + (v3.z + v3.w)))
                + (((v4.x + v4.y) + (v4.z + v4.w)) + ((v5.x + v5.y) + (v5.z + v5.w)))
                + (((v6.x + v6.y) + (v6.z + v6.w)) + ((v7.x + v7.y) + (v7.z + v7.w)));
        #pragma unroll
        for (int o = 16; o > 0; o >>= 1) s += __shfl_down_sync(0xffffffffu, s, o);
        if (lane == 0) wmn[wid] = s;
        __syncthreads();
        if (tid < 32) {
            float t = (tid < NW) ? wmn[tid] : 0.f;
            #pragma unroll
            for (int o = 4; o > 0; o >>= 1) t += __shfl_down_sync(0xffffffffu, t, o);
            if (tid == 0) g_centrality[r] = t / (float)M;
        }
        return;
    }

    // ==================== selection path ===============
    const int i = r;
    float mn = FLT_MAX, mx = -FLT_MAX, tm = -FLT_MAX;
    {
        const float4* rp = (const float4*)(sim + (size_t)i * B);
        const int dq = i >> 2, dl = i & 3;
        #pragma unroll
        for (int k = 0; k < 4; k++) {
            int j = tid + k * TPB;
            float4 v = rp[j];
            ((float4*)srow)[j] = v;                 // raw copy (diag present)
            if (j == dq) {                          // strip diag for stats only
                float dv = (dl == 0) ? v.x : (dl == 1) ? v.y : (dl == 2) ? v.z : v.w;
                g_diag[i] = dv;
                const float rep = (dl == 0) ? v.y : v.x;
                if (dl == 0) v.x = rep; else if (dl == 1) v.y = rep;
                else if (dl == 2) v.z = rep; else v.w = rep;
            }
            float lmx = fmaxf(fmaxf(v.x, v.y), fmaxf(v.z, v.w));
            mn = fminf(mn, fminf(fminf(v.x, v.y), fminf(v.z, v.w)));
            mx = fmaxf(mx, lmx);
            tm = fmaxf(tm, lmx);
        }
        if (tid < NBINS) hist[tid] = 0u;
        if (tid == 0) sh_cnt = 0u;
    }
    #pragma unroll
    for (int o = 16; o > 0; o >>= 1) {
        mn = fminf(mn, __shfl_xor_sync(0xffffffffu, mn, o));
        mx = fmaxf(mx, __shfl_xor_sync(0xffffffffu, mx, o));
    }
    if (lane == 0) { wmn[wid] = mn; wmx[wid] = mx; }
    __syncthreads();
    if (tid == 0) {
        float lo = wmn[0], hi = wmx[0];
        #pragma unroll
        for (int w = 1; w < NW; w++) { lo = fminf(lo, wmn[w]); hi = fmaxf(hi, wmx[w]); }
        sh_lo = lo;
        sh_scale = (float)NBINS / fmaxf(hi - lo, 1e-30f);
        g_mns[i] = lo;                              // mn_s = off-diag row min
    }
    __syncthreads();

    const float lo = sh_lo, scale = sh_scale;

    // histogram the 256 per-thread maxima (one atomic per thread)
    {
        int b = (int)((tm - lo) * scale);
        b = min(max(b, 0), NBINS - 1);
        atomicAdd(&hist[b], 1u);
    }
    __syncthreads();

    // b* = bin of the 33rd-largest thread-max (warp-0 suffix scan)
    if (wid == 0) {
        unsigned running = 0u;
        bool found = false;
        for (int c = 0; c < NBINS / 32 && !found; c++) {
            int bin = NBINS - 1 - c * 32 - lane;
            unsigned p = hist[bin];
            #pragma unroll
            for (int o = 1; o < 32; o <<= 1) {
                unsigned t = __shfl_up_sync(0xffffffffu, p, o);
                if (lane >= o) p += t;
            }
            unsigned cum = running + p;
            unsigned ball = __ballot_sync(0xffffffffu, cum >= 33u);
            running += __shfl_sync(0xffffffffu, p, 31);
            if (ball) {
                if (lane == 0) sh_bstar = NBINS - 1 - c * 32 - (__ffs(ball) - 1);
                found = true;
            }
        }
    }
    __syncthreads();

    // collect candidates with bin >= b*
    {
        const int bstar = sh_bstar;
        #pragma unroll
        for (int k = 0; k < 4; k++) {
            int j = tid + k * TPB;
            float4 v = ((const float4*)srow)[j];
            int base = j << 2;
            #pragma unroll
            for (int e = 0; e < 4; e++) {
                float f = (e == 0) ? v.x : (e == 1) ? v.y : (e == 2) ? v.z : v.w;
                int idx = base + e;
                int b = (int)((f - lo) * scale);
                b = min(max(b, 0), NBINS - 1);
                if (b >= bstar && idx != i) {
                    unsigned pos = atomicAdd(&sh_cnt, 1u);
                    if (pos < CAP) { cand_val[pos] = f; cand_idx[pos] = idx; }
                }
            }
        }
    }
    __syncthreads();

    // exact rank by counting (ties: lower index first, matches top_k)
    {
        int n = (int)min(sh_cnt, (unsigned)CAP);
        for (int c = tid; c < n; c += TPB) {
            float v = cand_val[c];
            int   id = cand_idx[c];
            int rk = 0;
            for (int d = 0; d < n; d++) {
                float vd = cand_val[d];
                rk += (vd > v) || (vd == v && cand_idx[d] < id);
            }
            if (rk < KNB) {
                g_tv[i][rk] = v;
                g_ti[i][rk] = id;
            } else if (rk == KNB) {
                g_mxs[i] = v;                       // mx_s = 33rd largest off-diag
            }
        }
    }
}

// ---------------------------------------------------------------------------
// Kernel B (grid = B/NW = 512): fused epilogue.
//   Phase 1: centrality top/bot-34 via THREAD-EXTREME PREFILTER (512 shared
//            atomics per CTA instead of 4096).
//   Phase 2: 8 warps x 1 row each -> g_rowloss.
//   Phase 3: last-CTA ticket -> deterministic mean into d_out.
// ---------------------------------------------------------------------------
__global__ __launch_bounds__(TPB) void epilogue_kernel(
    const float* __restrict__ temp_p, float* __restrict__ out, int B)
{
    __shared__ float    c[BMAX];
    __shared__ unsigned histT[NBINS], histB[NBINS];
    __shared__ float    tv[CECAP]; __shared__ int ti[CECAP];
    __shared__ float    bv[CECAP]; __shared__ int bi[CECAP];
    __shared__ float    stv[NEXT]; __shared__ int sti[NEXT];
    __shared__ float    sbv[NEXT]; __shared__ int sbi[NEXT];
    __shared__ float    wmn[NW], wmx[NW];
    __shared__ unsigned cntT, cntB;
    __shared__ int      sh_btop, sh_bbot;
    __shared__ float    sh_lo, sh_scale;

    const int tid = threadIdx.x, lane = tid & 31, wid = tid >> 5;

    // ---- Phase 1: stage c[], per-thread min/max of own 16 values ----
    float vv[BMAX / TPB];
    float mn = FLT_MAX, mx = -FLT_MAX;
    #pragma unroll
    for (int k = 0; k < BMAX / TPB; k++) {
        float v = g_centrality[tid + k * TPB];
        c[tid + k * TPB] = v;
        vv[k] = v;
        mn = fminf(mn, v); mx = fmaxf(mx, v);
    }
    const float tmin = mn, tmax = mx;               // thread extremes
    if (tid < NBINS) { histT[tid] = 0u; histB[tid] = 0u; }
    if (tid == 0) { cntT = 0u; cntB = 0u; }
    #pragma unroll
    for (int o = 16; o > 0; o >>= 1) {
        mn = fminf(mn, __shfl_xor_sync(0xffffffffu, mn, o));
        mx = fmaxf(mx, __shfl_xor_sync(0xffffffffu, mx, o));
    }
    if (lane == 0) { wmn[wid] = mn; wmx[wid] = mx; }
    __syncthreads();
    if (tid == 0) {
        float lo = wmn[0], hi = wmx[0];
        #pragma unroll
        for (int w = 1; w < NW; w++) { lo = fminf(lo, wmn[w]); hi = fmaxf(hi, wmx[w]); }
        sh_lo = lo;
        sh_scale = (float)NBINS / fmaxf(hi - lo, 1e-30f);
    }
    __syncthreads();
    {
        const float lo = sh_lo, scale = sh_scale;

        // histogram the 256 thread-maxes and 256 thread-mins (2 atomics/thread)
        {
            int bt = (int)((tmax - lo) * scale);
            bt = min(max(bt, 0), NBINS - 1);
            atomicAdd(&histT[bt], 1u);
            int bb = (int)((tmin - lo) * scale);
            bb = min(max(bb, 0), NBINS - 1);
            atomicAdd(&histB[bb], 1u);
        }
        __syncthreads();

        // parallel boundary scans: warp 0 -> btop (34th-largest thread-max),
        //                          warp 1 -> bbot (34th-smallest thread-min)
        if (wid == 0) {
            unsigned running = 0u;
            bool found = false;
            for (int cc = 0; cc < NBINS / 32 && !found; cc++) {
                int bin = NBINS - 1 - cc * 32 - lane;
                unsigned p = histT[bin];
                #pragma unroll
                for (int o = 1; o < 32; o <<= 1) {
                    unsigned t = __shfl_up_sync(0xffffffffu, p, o);
                    if (lane >= o) p += t;
                }
                unsigned cum = running + p;
                unsigned ball = __ballot_sync(0xffffffffu, cum >= NEXT);
                running += __shfl_sync(0xffffffffu, p, 31);
                if (ball) {
                    if (lane == 0) sh_btop = NBINS - 1 - cc * 32 - (__ffs(ball) - 1);
                    found = true;
                }
            }
            if (!found && lane == 0) sh_btop = 0;
        } else if (wid == 1) {
            unsigned running = 0u;
            bool found = false;
            for (int cc = 0; cc < NBINS / 32 && !found; cc++) {
                int bin = cc * 32 + lane;
                unsigned p = histB[bin];
                #pragma unroll
                for (int o = 1; o < 32; o <<= 1) {
                    unsigned t = __shfl_up_sync(0xffffffffu, p, o);
                    if (lane >= o) p += t;
                }
                unsigned cum = running + p;
                unsigned ball = __ballot_sync(0xffffffffu, cum >= NEXT);
                running += __shfl_sync(0xffffffffu, p, 31);
                if (ball) {
                    if (lane == 0) sh_bbot = cc * 32 + (__ffs(ball) - 1);
                    found = true;
                }
            }
            if (!found && lane == 0) sh_bbot = NBINS - 1;
        }
        __syncthreads();

        // collect from registers with float compares:
        //   bin(v) >= btop  <=>  (v-lo)*scale >= (float)btop
        //   bin(v) <= bbot  <=>  (v-lo)*scale <  (float)(bbot+1)
        {
            const float thrT = (float)sh_btop;
            const float thrB = (float)(sh_bbot + 1);
            #pragma unroll
            for (int k = 0; k < BMAX / TPB; k++) {
                float v = vv[k];
                float key = (v - lo) * scale;
                int idx = tid + k * TPB;
                if (key >= thrT) {
                    unsigned p = atomicAdd(&cntT, 1u);
                    if (p < CECAP) { tv[p] = v; ti[p] = idx; }
                }
                if (key < thrB) {
                    unsigned p = atomicAdd(&cntB, 1u);
                    if (p < CECAP) { bv[p] = v; bi[p] = idx; }
                }
            }
        }
        __syncthreads();
        int n = (int)min(cntT, (unsigned)CECAP);
        for (int q = tid; q < n; q += TPB) {
            float v = tv[q]; int id = ti[q]; int rk = 0;
            for (int d = 0; d < n; d++) {
                float vd = tv[d];
                rk += (vd > v) || (vd == v && ti[d] < id);
            }
            if (rk < NEXT) { stv[rk] = v; sti[rk] = id; }
        }
        n = (int)min(cntB, (unsigned)CECAP);
        for (int q = tid; q < n; q += TPB) {
            float v = bv[q]; int id = bi[q]; int rk = 0;
            for (int d = 0; d < n; d++) {
                float vd = bv[d];
                rk += (vd < v) || (vd == v && bi[d] < id);
            }
            if (rk < NEXT) { sbv[rk] = v; sbi[rk] = id; }
        }
    }
    __syncthreads();

    // ---- Phase 2: one warp per row ----
    {
        const int r = blockIdx.x * NW + wid;
        float tv2 = g_tv[r][lane];
        int   ti2 = g_ti[r][lane];
        float dg  = g_diag[r];
        const float mn_s = g_mns[r], mx_s = g_mxs[r];

        // centrality extremes over non-excluded (32 neighbors + diagonal r)
        float mx_c = stv[NEXT - 1];
        for (int e = 0; e < NEXT; e++) {
            int id = sti[e];
            bool excl = (__ballot_sync(0xffffffffu, ti2 == id) != 0u) || (id == r);
            if (!excl) { mx_c = stv[e]; break; }
        }
        float mn_c = sbv[NEXT - 1];
        for (int e = 0; e < NEXT; e++) {
            int id = sbi[e];
            bool excl = (__ballot_sync(0xffffffffu, ti2 == id) != 0u) || (id == r);
            if (!excl) { mn_c = sbv[e]; break; }
        }

        // logsumexp over extended set (32 neighbors + diagonal)
        float m = tv2;
        #pragma unroll
        for (int o = 16; o > 0; o >>= 1) m = fmaxf(m, __shfl_xor_sync(0xffffffffu, m, o));
        m = fmaxf(m, dg);
        float s = expf(tv2 - m);
        #pragma unroll
        for (int o = 16; o > 0; o >>= 1) s += __shfl_xor_sync(0xffffffffu, s, o);
        s += expf(dg - m);
        float lse = logf(s) + m;

        // positive weights: softmax over neighbors of (norm_sim - norm_cent)*T
        float T  = *temp_p;
        float ns = (tv2 - mn_s) / (mx_s - mn_s);
        float nc = (c[ti2] - mn_c) / (mx_c - mn_c);   // smem-staged centrality
        float a  = (ns - nc) * T;
        float am = a;
        #pragma unroll
        for (int o = 16; o > 0; o >>= 1) am = fmaxf(am, __shfl_xor_sync(0xffffffffu, am, o));
        float pe = expf(a - am);
        float ps = pe;
        #pragma unroll
        for (int o = 16; o > 0; o >>= 1) ps += __shfl_xor_sync(0xffffffffu, ps, o);
        float pw = pe / ps;

        float num   = pw * (tv2 - lse);
        float pwsum = pw;
        #pragma unroll
        for (int o = 16; o > 0; o >>= 1) {
            num   += __shfl_xor_sync(0xffffffffu, num,   o);
            pwsum += __shfl_xor_sync(0xffffffffu, pwsum, o);
        }
        if (lane == 0) {
            g_rowloss[r] = -(num + (dg - lse)) / (pwsum + 1.0f);
        }
    }

    // ---- Phase 3: last-CTA ticket -> deterministic mean ----
    __shared__ bool is_last;
    __syncthreads();
    if (tid == 0) {
        __threadfence();                            // publish this CTA's rows
        unsigned o = atomicAdd(&g_tick, 1u);
        is_last = (o == (unsigned)gridDim.x - 1u);
        if (is_last) g_tick = 0u;                   // reset for graph replay
    }
    __syncthreads();
    if (!is_last) return;
    __threadfence();                                // see all rows

    float s = 0.f;
    {
        const float4* p = (const float4*)g_rowloss;    // 1024 float4
        float4 a0 = p[tid];
        float4 a1 = p[tid + TPB];
        float4 a2 = p[tid + 2 * TPB];
        float4 a3 = p[tid + 3 * TPB];
        s = (((a0.x + a0.y) + (a0.z + a0.w)) + ((a1.x + a1.y) + (a1.z + a1.w)))
          + (((a2.x + a2.y) + (a2.z + a2.w)) + ((a3.x + a3.y) + (a3.z + a3.w)));
    }
    __shared__ float wsd[NW];
    #pragma unroll
    for (int o = 16; o > 0; o >>= 1) s += __shfl_down_sync(0xffffffffu, s, o);
    if (lane == 0) wsd[wid] = s;
    __syncthreads();
    if (tid < 32) {
        float t = (tid < NW) ? wsd[tid] : 0.f;
        #pragma unroll
        for (int o = 4; o > 0; o >>= 1) t += __shfl_down_sync(0xffffffffu, t, o);
        if (tid == 0) out[0] = t / (float)B;
    }
}

// ---------------------------------------------------------------------------
extern "C" void kernel_launch(void* const* d_in, const int* in_sizes, int n_in,
                              void* d_out, int out_size)
{
    const float* sim  = (const float*)d_in[0];
    const float* mem  = (const float*)d_in[1];
    const float* temp = (const float*)d_in[n_in - 1];

    int nsim = in_sizes[0];
    int B = 1;
    while ((long long)B * B < (long long)nsim) B <<= 1;   // B = 4096
    int M = in_sizes[1] / B;                               // M = 8192

    combined_kernel<<<2 * B, TPB>>>(sim, mem, B, M);
    epilogue_kernel<<<B / NW, TPB>>>(temp, (float*)d_out, B);
}